// round 15
// baseline (speedup 1.0000x reference)
#include <cuda_runtime.h>
#include <cuda_fp16.h>
#include <math.h>
#include <stdint.h>

// Problem constants
#define BB 2
#define TT 2048
#define DD 1024
#define HH 16
#define HD 64
#define MM (BB*TT)   // 4096

// ---------------------------------------------------------------------------
// Scratch (device globals; no allocation allowed)
// ---------------------------------------------------------------------------
__device__ float g_c[BB*HH*TT];

__device__ __half g_xhi[MM*DD], g_xlo[MM*DD];
__device__ __half g_qhi[MM*DD], g_qlo[MM*DD];        // [B,H,T,HD]
__device__ __half g_khi[MM*DD], g_klo[MM*DD];
__device__ __half g_vhi[MM*DD], g_vlo[MM*DD];
__device__ __half g_ohi[MM*DD];
__device__ __half g_wqh[DD*DD];
__device__ __half g_wkh[DD*DD];
__device__ __half g_wvh[DD*DD];
__device__ __half g_woh[DD*DD];
__device__ __half g_wfth[HH*DD], g_wftl[HH*DD];

// ---------------------------------------------------------------------------
// PTX helpers
// ---------------------------------------------------------------------------
__device__ __forceinline__ uint32_t smem_u32(const void* p) {
    uint32_t a;
    asm("{ .reg .u64 t; cvta.to.shared.u64 t, %1; cvt.u32.u64 %0, t; }"
        : "=r"(a) : "l"(p));
    return a;
}
__device__ __forceinline__ void cp16(uint32_t dst, const void* src) {
    asm volatile("cp.async.cg.shared.global [%0], [%1], 16;"
                 :: "r"(dst), "l"(src) : "memory");
}
__device__ __forceinline__ void cp_commit() {
    asm volatile("cp.async.commit_group;" ::: "memory");
}
template<int N> __device__ __forceinline__ void cp_wait() {
    asm volatile("cp.async.wait_group %0;" :: "n"(N) : "memory");
}
__device__ __forceinline__ void ldmx4(uint32_t* r, uint32_t addr) {
    asm volatile("ldmatrix.sync.aligned.m8n8.x4.shared.b16 {%0,%1,%2,%3}, [%4];"
                 : "=r"(r[0]), "=r"(r[1]), "=r"(r[2]), "=r"(r[3]) : "r"(addr));
}
__device__ __forceinline__ void ldmx4t(uint32_t* r, uint32_t addr) {
    asm volatile("ldmatrix.sync.aligned.m8n8.x4.trans.shared.b16 {%0,%1,%2,%3}, [%4];"
                 : "=r"(r[0]), "=r"(r[1]), "=r"(r[2]), "=r"(r[3]) : "r"(addr));
}
__device__ __forceinline__ void mma16816(float* c, const uint32_t* a,
                                         uint32_t b0, uint32_t b1) {
    asm volatile(
        "mma.sync.aligned.m16n8k16.row.col.f32.f16.f16.f32 "
        "{%0,%1,%2,%3}, {%4,%5,%6,%7}, {%8,%9}, {%0,%1,%2,%3};"
        : "+f"(c[0]), "+f"(c[1]), "+f"(c[2]), "+f"(c[3])
        : "r"(a[0]), "r"(a[1]), "r"(a[2]), "r"(a[3]), "r"(b0), "r"(b1));
}
__device__ __forceinline__ float ex2f(float x) {
    float r;
    asm("ex2.approx.ftz.f32 %0, %1;" : "=f"(r) : "f"(x));
    return r;
}
__device__ __forceinline__ void pack_split(float a, float b,
                                           uint32_t& hi, uint32_t& lo) {
    __half ha = __float2half_rn(a);
    __half hb = __float2half_rn(b);
    __half la = __float2half_rn(a - __half2float(ha));
    __half lb = __float2half_rn(b - __half2float(hb));
    __half2 H = __halves2half2(ha, hb);
    __half2 L = __halves2half2(la, lb);
    hi = *reinterpret_cast<uint32_t*>(&H);
    lo = *reinterpret_cast<uint32_t*>(&L);
}
__device__ __forceinline__ uint32_t pack_h(float a, float b) {
    __half2 H = __halves2half2(__float2half_rn(a), __float2half_rn(b));
    return *reinterpret_cast<uint32_t*>(&H);
}

#define LOG2E 1.44269504088896340736f

__device__ __forceinline__ uint32_t asw(int row, int chunk) {
    return (uint32_t)(row * 128 + ((chunk ^ (row & 7)) * 16));
}

// ---------------------------------------------------------------------------
// Fused preprocessing
// ---------------------------------------------------------------------------
__global__ __launch_bounds__(256) void prep_kernel(
    const float* __restrict__ x,
    const float* __restrict__ W0, const float* __restrict__ W1,
    const float* __restrict__ W2, const float* __restrict__ W3,
    const float* __restrict__ Wf,
    __half* __restrict__ xhi, __half* __restrict__ xlo,
    __half* __restrict__ H0, __half* __restrict__ H1,
    __half* __restrict__ H2, __half* __restrict__ H3,
    __half* __restrict__ Th, __half* __restrict__ Tl)
{
    __shared__ float t[32][33];
    const int bid = blockIdx.x;
    const int tid = threadIdx.x;

    if (bid < 4096) {
        int i = bid * 256 + tid;
        float4 v = ((const float4*)x)[i];
        uint32_t h0, l0, h1, l1;
        pack_split(v.x, v.y, h0, l0);
        pack_split(v.z, v.w, h1, l1);
        ((uint32_t*)xhi)[2*i]   = h0;
        ((uint32_t*)xhi)[2*i+1] = h1;
        ((uint32_t*)xlo)[2*i]   = l0;
        ((uint32_t*)xlo)[2*i+1] = l1;
    } else if (bid < 8192) {
        const int inner = bid - 4096;
        const int z = inner >> 10;
        const int rem = inner & 1023;
        const int bx = (rem & 31) * 32;
        const int by = (rem >> 5) * 32;
        const float* W  = (z == 0) ? W0 : (z == 1) ? W1 : (z == 2) ? W2 : W3;
        __half* Whi     = (z == 0) ? H0 : (z == 1) ? H1 : (z == 2) ? H2 : H3;
        const int tx = tid & 31, ty = tid >> 5;
#pragma unroll
        for (int j = 0; j < 32; j += 8)
            t[ty + j][tx] = W[(size_t)(by + ty + j) * DD + bx + tx];
        __syncthreads();
#pragma unroll
        for (int j = 0; j < 32; j += 8) {
            float v = t[tx][ty + j];
            Whi[(size_t)(bx + ty + j) * DD + by + tx] = __float2half_rn(v);
        }
    } else {
        int idx = (bid - 8192) * 256 + tid;
        int h = idx >> 10;
        int d = idx & 1023;
        float v = Wf[d * HH + h];
        __half hi = __float2half_rn(v);
        __half lo = __float2half_rn(v - __half2float(hi));
        Th[h * DD + d] = hi;
        Tl[h * DD + d] = lo;
    }
}

// ---------------------------------------------------------------------------
// Big GEMM core (unchanged from R14)
// ---------------------------------------------------------------------------
#define GT     16384
#define GSTG   (2*GT)
#define GEMM_SMEM (3*GSTG)   // 98304
#define EPIT   (128*272)

template<typename EPILOG>
__device__ __forceinline__ void gemm1p_body(
    uint32_t smb, char* smraw, int tid,
    const __half* a_h, const __half* b_h,
    EPILOG epi)
{
    const int wid  = tid >> 5;
    const int lane = tid & 31;
    const int wm = (wid & 1) * 64;
    const int wn = (wid >> 1) * 64;

    float acc[4][8][4];
#pragma unroll
    for (int i = 0; i < 4; i++)
#pragma unroll
        for (int j = 0; j < 8; j++)
#pragma unroll
            for (int k = 0; k < 4; k++) acc[i][j][k] = 0.f;

    const int a_row = lane & 15;
    const int a_chk = lane >> 4;
    const int b_mat = lane >> 3;
    const int b_row = (b_mat >> 1) * 8 + (lane & 7);
    const int b_chk = b_mat & 1;

    auto stage = [&](uint32_t sbase, int k0) {
        const __half* bases[2] = { a_h + k0, b_h + k0 };
#pragma unroll
        for (int mat = 0; mat < 2; mat++) {
#pragma unroll
            for (int i = 0; i < 8; i++) {
                int s = tid + i * 128;
                int row = s >> 3, c = s & 7;
                cp16(sbase + mat * GT + asw(row, c),
                     bases[mat] + (size_t)row * DD + c * 8);
            }
        }
    };

    stage(smb, 0);
    cp_commit();
    stage(smb + GSTG, 64);
    cp_commit();

    for (int it = 0; it < 16; it++) {
        if (it + 2 < 16) cp_wait<1>(); else cp_wait<0>();
        __syncthreads();
        if (it + 2 < 16) {
            stage(smb + ((it + 2) % 3) * GSTG, (it + 2) * 64);
            cp_commit();
        }

        const uint32_t sb = smb + (it % 3) * GSTG;
#pragma unroll
        for (int ks = 0; ks < 4; ks++) {
            uint32_t af[4][4], bf[4][4];
#pragma unroll
            for (int mt = 0; mt < 4; mt++)
                ldmx4(af[mt], sb + asw(wm + mt * 16 + a_row, ks * 2 + a_chk));
#pragma unroll
            for (int ng = 0; ng < 4; ng++)
                ldmx4(bf[ng], sb + GT + asw(wn + ng * 16 + b_row, ks * 2 + b_chk));
#pragma unroll
            for (int mt = 0; mt < 4; mt++)
#pragma unroll
                for (int ng = 0; ng < 4; ng++)
#pragma unroll
                    for (int h = 0; h < 2; h++)
                        mma16816(acc[mt][ng * 2 + h], af[mt],
                                 bf[ng][h * 2], bf[ng][h * 2 + 1]);
        }
    }

    epi(acc, wm, wn, lane, wid);
}

// ---------------------------------------------------------------------------
// Forget-gate device path (unchanged)
// ---------------------------------------------------------------------------
#define FG_XL   16384
#define FG_WH   32768
#define FG_WL   34816
#define FG_STG  36864

__device__ void forget_body(
    char* smraw, uint32_t smb, int tid, int m0,
    const __half* __restrict__ xhi, const __half* __restrict__ xlo,
    const __half* __restrict__ wfh, const __half* __restrict__ wfl,
    const float* __restrict__ bf, float* __restrict__ lf)
{
    const int wid  = tid >> 5;
    const int lane = tid & 31;
    const int wm = wid * 32;

    const __half* xh_ = xhi + (size_t)m0 * DD;
    const __half* xl_ = xlo + (size_t)m0 * DD;

    float acc[2][2][4];
#pragma unroll
    for (int i = 0; i < 2; i++)
#pragma unroll
        for (int j = 0; j < 2; j++)
#pragma unroll
            for (int k = 0; k < 4; k++) acc[i][j][k] = 0.f;

    const int a_row = lane & 15;
    const int a_chk = lane >> 4;
    const int b_mat = lane >> 3;
    const int b_row = (b_mat >> 1) * 8 + (lane & 7);
    const int b_chk = b_mat & 1;

    auto stage = [&](uint32_t sbase, int k0) {
#pragma unroll
        for (int i = 0; i < 8; i++) {
            int s = tid + i * 128;
            int row = s >> 3, c = s & 7;
            cp16(sbase + asw(row, c),         xh_ + (size_t)row * DD + k0 + c * 8);
            cp16(sbase + FG_XL + asw(row, c), xl_ + (size_t)row * DD + k0 + c * 8);
        }
        {
            int row = tid >> 3, c = tid & 7;
            cp16(sbase + FG_WH + asw(row, c), wfh + (size_t)row * DD + k0 + c * 8);
            cp16(sbase + FG_WL + asw(row, c), wfl + (size_t)row * DD + k0 + c * 8);
        }
    };

    stage(smb, 0);
    cp_commit();

    for (int it = 0; it < 16; it++) {
        if (it + 1 < 16) {
            stage(smb + ((it + 1) & 1) * FG_STG, (it + 1) * 64);
            cp_commit();
            cp_wait<1>();
        } else {
            cp_wait<0>();
        }
        __syncthreads();

        const uint32_t sb = smb + (it & 1) * FG_STG;
#pragma unroll
        for (int ks = 0; ks < 4; ks++) {
            uint32_t ah[2][4], al[2][4], bh[4], bl[4];
#pragma unroll
            for (int mt = 0; mt < 2; mt++) {
                uint32_t aoff = asw(wm + mt * 16 + a_row, ks * 2 + a_chk);
                ldmx4(ah[mt], sb + aoff);
                ldmx4(al[mt], sb + FG_XL + aoff);
            }
            {
                uint32_t boff = asw(b_row, ks * 2 + b_chk);
                ldmx4(bh, sb + FG_WH + boff);
                ldmx4(bl, sb + FG_WL + boff);
            }
#pragma unroll
            for (int mt = 0; mt < 2; mt++)
#pragma unroll
                for (int h = 0; h < 2; h++) {
                    float* c = acc[mt][h];
                    mma16816(c, ah[mt], bh[h * 2], bh[h * 2 + 1]);
                    mma16816(c, ah[mt], bl[h * 2], bl[h * 2 + 1]);
                    mma16816(c, al[mt], bh[h * 2], bh[h * 2 + 1]);
                }
        }
        __syncthreads();
    }

    const int r0 = lane >> 2;
    const int cpair = (lane & 3) * 2;
#pragma unroll
    for (int mt = 0; mt < 2; mt++) {
#pragma unroll
        for (int nt = 0; nt < 2; nt++) {
            const int h0 = nt * 8 + cpair;
            const float bf0 = bf[h0], bf1 = bf[h0 + 1];
#pragma unroll
            for (int half = 0; half < 2; half++) {
                const int m = m0 + wm + mt * 16 + r0 + half * 8;
                const int b = m >> 11;
                const int t = m & (TT - 1);
                float z0 = acc[mt][nt][half * 2]     + bf0;
                float z1 = acc[mt][nt][half * 2 + 1] + bf1;
                float ls0 = (z0 >= 0.f) ? -log1pf(__expf(-z0))
                                        : z0 - log1pf(__expf(z0));
                float ls1 = (z1 >= 0.f) ? -log1pf(__expf(-z1))
                                        : z1 - log1pf(__expf(z1));
                ls0 = fminf(fmaxf(ls0, -10.f), 0.f);
                ls1 = fminf(fmaxf(ls1, -10.f), 0.f);
                lf[(size_t)(b * HH + h0)     * TT + t] = ls0;
                lf[(size_t)(b * HH + h0 + 1) * TT + t] = ls1;
            }
        }
    }
}

// ---------------------------------------------------------------------------
// Union kernel: QKV GEMM (blockIdx.x < 24) + forget gate (blockIdx.x == 24).
// ---------------------------------------------------------------------------
__global__ __launch_bounds__(128, 2) void gemm_qkv_forget(
    const __half* __restrict__ xh, const __half* __restrict__ xlo,
    const __half* __restrict__ wqh, const __half* __restrict__ wkh,
    const __half* __restrict__ wvh,
    const __half* __restrict__ wfh, const __half* __restrict__ wfl,
    const float* __restrict__ bf, float* __restrict__ lf,
    __half* __restrict__ qhi, __half* __restrict__ qlo,
    __half* __restrict__ khi, __half* __restrict__ klo,
    __half* __restrict__ vhi, __half* __restrict__ vlo)
{
    extern __shared__ char smraw[];
    const uint32_t smb = smem_u32(smraw);
    const int tid = threadIdx.x;

    if (blockIdx.x == 24) {
        forget_body(smraw, smb, tid, blockIdx.y * 128,
                    xh, xlo, wfh, wfl, bf, lf);
        return;
    }

    const int nmat = blockIdx.x >> 3;
    const int nloc = (blockIdx.x & 7) * 128;
    const int m0 = blockIdx.y * 128;

    const __half* a_h = xh + (size_t)m0 * DD;
    const __half* b_h = ((nmat == 0) ? wqh : (nmat == 1) ? wkh : wvh)
                        + (size_t)nloc * DD;
    __half* Chi = (nmat == 0) ? qhi : (nmat == 1) ? khi : vhi;
    __half* Clo = (nmat == 0) ? qlo : (nmat == 1) ? klo : vlo;

    gemm1p_body(smb, smraw, tid, a_h, b_h,
        [&](float acc[4][8][4], int wm, int wn, int lane, int wid) {
            __syncthreads();
            char* Sh = smraw;
            char* Sl = smraw + EPIT;
            const int r0 = lane >> 2;
            const int cpair = (lane & 3) * 2;
#pragma unroll
            for (int mt = 0; mt < 4; mt++) {
#pragma unroll
                for (int nt = 0; nt < 8; nt++) {
                    const int row0 = wm + mt * 16 + r0;
                    const int col  = wn + nt * 8 + cpair;
                    uint32_t h0, l0, h1, l1;
                    pack_split(acc[mt][nt][0], acc[mt][nt][1], h0, l0);
                    pack_split(acc[mt][nt][2], acc[mt][nt][3], h1, l1);
                    *(uint32_t*)(Sh + row0 * 272 + col * 2) = h0;
                    *(uint32_t*)(Sl + row0 * 272 + col * 2) = l0;
                    *(uint32_t*)(Sh + (row0 + 8) * 272 + col * 2) = h1;
                    *(uint32_t*)(Sl + (row0 + 8) * 272 + col * 2) = l1;
                }
            }
            __syncthreads();

            const int g  = lane >> 3;
            const int ck = lane & 7;
#pragma unroll
            for (int p = 0; p < 32; p++) {
                int flat = p * 16 + wid * 4 + g;
                int hl  = flat >> 8;
                int rem = flat & 255;
                int hh  = rem >> 7;
                int mm  = rem & 127;
                uint4 v = *(uint4*)(smraw + hl * EPIT + mm * 272
                                    + hh * 128 + ck * 16);
                const int m = m0 + mm;
                const int b = m >> 11;
                const int t = m & (TT - 1);
                const int h = (nloc >> 6) + hh;
                __half* dst = (hl == 0 ? Chi : Clo)
                            + (((size_t)((b * HH + h) * TT + t)) << 6) + ck * 8;
                *(uint4*)dst = v;
            }
        });
}

// ---------------------------------------------------------------------------
// Output GEMM
// ---------------------------------------------------------------------------
__global__ __launch_bounds__(128, 2) void gemm_out(
    const __half* __restrict__ Ah,
    const __half* __restrict__ Bhi,
    float* __restrict__ Cf)
{
    extern __shared__ char smraw[];
    const uint32_t smb = smem_u32(smraw);
    const int tid = threadIdx.x;
    const int n0 = blockIdx.x * 128;
    const int m0 = blockIdx.y * 128;

    const __half* a_h = Ah + (size_t)m0 * DD;
    const __half* b_h = Bhi + (size_t)n0 * DD;

    gemm1p_body(smb, smraw, tid, a_h, b_h,
        [&](float acc[4][8][4], int wm, int wn, int lane, int wid) {
            (void)wid;
            const int r0 = lane >> 2;
            const int cpair = (lane & 3) * 2;
#pragma unroll
            for (int mt = 0; mt < 4; mt++) {
#pragma unroll
                for (int nt = 0; nt < 8; nt++) {
                    const int m = m0 + wm + mt * 16 + r0;
                    const int n = n0 + wn + nt * 8 + cpair;
                    float* dst0 = Cf + (size_t)m * DD + n;
                    float* dst1 = Cf + (size_t)(m + 8) * DD + n;
                    *(float2*)dst0 = make_float2(acc[mt][nt][0], acc[mt][nt][1]);
                    *(float2*)dst1 = make_float2(acc[mt][nt][2], acc[mt][nt][3]);
                }
            }
        });
}

// ---------------------------------------------------------------------------
// Cumsum over T per (b,h)
// ---------------------------------------------------------------------------
__global__ __launch_bounds__(256) void cumsum_kernel(float* __restrict__ lf)
{
    const int bh = blockIdx.x;
    float* p = lf + (size_t)bh * TT;
    const int tid = threadIdx.x;
    const int lane = tid & 31, wid = tid >> 5;
    __shared__ float wsum[8];

    float v[8];
    float s = 0.f;
#pragma unroll
    for (int i = 0; i < 8; i++) { v[i] = p[tid * 8 + i]; s += v[i]; }

    float ss = s;
#pragma unroll
    for (int off = 1; off < 32; off <<= 1) {
        float n = __shfl_up_sync(0xffffffffu, ss, off);
        if (lane >= off) ss += n;
    }
    if (lane == 31) wsum[wid] = ss;
    __syncthreads();
    float woff = 0.f;
#pragma unroll
    for (int w = 0; w < 8; w++)
        if (w < wid) woff += wsum[w];

    float run = woff + ss - s;
#pragma unroll
    for (int i = 0; i < 8; i++) { run += v[i]; p[tid * 8 + i] = run; }
}

// ---------------------------------------------------------------------------
// HMMA forgetting attention: 128 q-rows per block, 256 threads (8 warps x 16).
// K/V traffic halves vs 64-row blocks; causal mask via global indices.
// ---------------------------------------------------------------------------
#define ATILE  8192
#define ACKS   (4*ATILE)
#define ASTAGE (4*ATILE + 256)
#define AQOFF  (2*ASTAGE)
#define AQT    16384                       // 128-row Q tile
#define ATTN_SMEM (2*ASTAGE + 2*AQT)       // 98816

__device__ __forceinline__ void attn_stage(
    uint32_t sb,
    const __half* Kh, const __half* Kl,
    const __half* Vh, const __half* Vl,
    const float* cptr, int k0, int tid)
{
    const __half* mats[4] = {
        Kh + (size_t)k0 * HD, Kl + (size_t)k0 * HD,
        Vh + (size_t)k0 * HD, Vl + (size_t)k0 * HD };
#pragma unroll
    for (int mt = 0; mt < 4; mt++) {
#pragma unroll
        for (int i = 0; i < 2; i++) {
            int s = tid + i * 256;
            int row = s >> 3, c = s & 7;
            cp16(sb + mt * ATILE + asw(row, c), mats[mt] + row * HD + c * 8);
        }
    }
    if (tid < 16) cp16(sb + ACKS + tid * 16, cptr + k0 + tid * 4);
}

__global__ __launch_bounds__(256, 1) void attn_mma(
    const __half* __restrict__ Qhi, const __half* __restrict__ Qlo,
    const __half* __restrict__ Khi, const __half* __restrict__ Klo,
    const __half* __restrict__ Vhi, const __half* __restrict__ Vlo,
    const float* __restrict__ C,
    __half* __restrict__ Ohi)
{
    extern __shared__ char smraw[];
    const uint32_t smb = smem_u32(smraw);

    const int tid  = threadIdx.x;
    const int wid  = tid >> 5;            // 0..7
    const int lane = tid & 31;
    const int qb = blockIdx.x;            // 0..15 (128-row blocks)
    const int bh = blockIdx.y;
    const int q0 = qb * 128;
    const int qt_hi = qb * 2 + 1;         // last 64-key tile index

    const __half* Qh = Qhi + (size_t)bh * TT * HD;
    const __half* Ql = Qlo + (size_t)bh * TT * HD;
    const __half* Kh = Khi + (size_t)bh * TT * HD;
    const __half* Kl = Klo + (size_t)bh * TT * HD;
    const __half* Vh = Vhi + (size_t)bh * TT * HD;
    const __half* Vl = Vlo + (size_t)bh * TT * HD;
    const float* cptr = C + (size_t)bh * TT;

    // union decay window across 128 rows: row q0 has the largest c.
    int kt_start;
    {
        const float cq0v = cptr[q0];
        int lo = 0, hi = qt_hi;
        while (lo < hi) {
            int mid = (lo + hi) >> 1;
            if (cq0v - cptr[mid * 64 + 63] >= -32.f) hi = mid;
            else lo = mid + 1;
        }
        kt_start = lo;
    }

    // Q tile 128 rows (hi + lo): 2048 cp16 / 256 threads = 8 each
#pragma unroll
    for (int i = 0; i < 8; i++) {
        int s = tid + i * 256;
        int mat = s >> 10;
        int rc = s & 1023;
        int row = rc >> 3, c = rc & 7;
        const __half* src = (mat == 0 ? Qh : Ql);
        cp16(smb + AQOFF + mat * AQT + asw(row, c),
             src + (size_t)(q0 + row) * HD + c * 8);
    }
    cp_commit();
    attn_stage(smb + (kt_start & 1) * ASTAGE, Kh, Kl, Vh, Vl, cptr,
               kt_start * 64, tid);
    cp_commit();

    cp_wait<1>();
    __syncthreads();

    const int a_row = lane & 15;
    const int a_chk = lane >> 4;
    uint32_t qh[4][4], ql[4][4];
#pragma unroll
    for (int ks = 0; ks < 4; ks++) {
        uint32_t ad = smb + AQOFF + asw(wid * 16 + a_row, ks * 2 + a_chk);
        ldmx4(qh[ks], ad);
        ldmx4(ql[ks], ad + AQT);
    }

    const int r0 = wid * 16 + (lane >> 2);   // 0..127
    const float cq0 = cptr[q0 + r0];
    const float cq1 = cptr[q0 + r0 + 8];
    const int qg0 = q0 + r0;
    const int qg1 = q0 + r0 + 8;

    float m0 = -1e30f, m1 = -1e30f, l0 = 0.f, l1 = 0.f;
    float o[8][4];
#pragma unroll
    for (int i = 0; i < 8; i++)
#pragma unroll
        for (int j = 0; j < 4; j++) o[i][j] = 0.f;

    const int b_mat = lane >> 3;
    const int b_row = (b_mat >> 1) * 8 + (lane & 7);
    const int b_chk = b_mat & 1;
    const int v_g = lane >> 3;
    const int v_r = lane & 7;

    for (int kt = kt_start; kt <= qt_hi; kt++) {
        if (kt < qt_hi) {
            attn_stage(smb + ((kt + 1) & 1) * ASTAGE,
                       Kh, Kl, Vh, Vl, cptr, (kt + 1) * 64, tid);
            cp_commit();
            cp_wait<1>();
        } else {
            cp_wait<0>();
        }
        __syncthreads();

        const uint32_t sb = smb + (kt & 1) * ASTAGE;
        const float* cks = (const float*)(smraw + (kt & 1) * ASTAGE + ACKS);

        float s[8][4];
#pragma unroll
        for (int i = 0; i < 8; i++)
#pragma unroll
            for (int j = 0; j < 4; j++) s[i][j] = 0.f;

#pragma unroll
        for (int ks = 0; ks < 4; ks++) {
            uint32_t kh[4][4], kl[4][4];
#pragma unroll
            for (int ng = 0; ng < 4; ng++) {
                uint32_t bd = sb + asw(ng * 16 + b_row, ks * 2 + b_chk);
                ldmx4(kh[ng], bd);
                ldmx4(kl[ng], bd + ATILE);
            }
#pragma unroll
            for (int ng = 0; ng < 4; ng++)
#pragma unroll
                for (int h = 0; h < 2; h++) {
                    float* c = s[ng * 2 + h];
                    mma16816(c, qh[ks], kh[ng][h * 2], kh[ng][h * 2 + 1]);
                    mma16816(c, qh[ks], kl[ng][h * 2], kl[ng][h * 2 + 1]);
                    mma16816(c, ql[ks], kh[ng][h * 2], kh[ng][h * 2 + 1]);
                }
        }

        const int k0g = kt * 64;
#pragma unroll
        for (int nt = 0; nt < 8; nt++) {
            const int col = nt * 8 + (lane & 3) * 2;
            const float ck0 = cks[col], ck1 = cks[col + 1];
            float d00 = fmaxf(cq0 - ck0, -50.f);
            float d01 = fmaxf(cq0 - ck1, -50.f);
            float d10 = fmaxf(cq1 - ck0, -50.f);
            float d11 = fmaxf(cq1 - ck1, -50.f);
            s[nt][0] = fmaf(s[nt][0], 0.125f, d00);
            s[nt][1] = fmaf(s[nt][1], 0.125f, d01);
            s[nt][2] = fmaf(s[nt][2], 0.125f, d10);
            s[nt][3] = fmaf(s[nt][3], 0.125f, d11);
            // causal mask via global indices (covers diag + beyond-range tiles)
            if (k0g + col     > qg0) s[nt][0] = -1e30f;
            if (k0g + col + 1 > qg0) s[nt][1] = -1e30f;
            if (k0g + col     > qg1) s[nt][2] = -1e30f;
            if (k0g + col + 1 > qg1) s[nt][3] = -1e30f;
        }

        float ml0 = -1e30f, ml1 = -1e30f;
#pragma unroll
        for (int nt = 0; nt < 8; nt++) {
            ml0 = fmaxf(ml0, fmaxf(s[nt][0], s[nt][1]));
            ml1 = fmaxf(ml1, fmaxf(s[nt][2], s[nt][3]));
        }
        ml0 = fmaxf(ml0, __shfl_xor_sync(0xffffffffu, ml0, 1));
        ml0 = fmaxf(ml0, __shfl_xor_sync(0xffffffffu, ml0, 2));
        ml1 = fmaxf(ml1, __shfl_xor_sync(0xffffffffu, ml1, 1));
        ml1 = fmaxf(ml1, __shfl_xor_sync(0xffffffffu, ml1, 2));
        const float mn0 = fmaxf(m0, ml0);
        const float mn1 = fmaxf(m1, ml1);
        const float corr0 = ex2f((m0 - mn0) * LOG2E);
        const float corr1 = ex2f((m1 - mn1) * LOG2E);
        m0 = mn0; m1 = mn1;

        float sum0 = 0.f, sum1 = 0.f;
#pragma unroll
        for (int nt = 0; nt < 8; nt++) {
            s[nt][0] = ex2f((s[nt][0] - mn0) * LOG2E);
            s[nt][1] = ex2f((s[nt][1] - mn0) * LOG2E);
            s[nt][2] = ex2f((s[nt][2] - mn1) * LOG2E);
            s[nt][3] = ex2f((s[nt][3] - mn1) * LOG2E);
            sum0 += s[nt][0] + s[nt][1];
            sum1 += s[nt][2] + s[nt][3];
        }
        l0 = l0 * corr0 + sum0;
        l1 = l1 * corr1 + sum1;
#pragma unroll
        for (int nt = 0; nt < 8; nt++) {
            o[nt][0] *= corr0; o[nt][1] *= corr0;
            o[nt][2] *= corr1; o[nt][3] *= corr1;
        }

        uint32_t ph[4][4], pl[4][4];
#pragma unroll
        for (int kc = 0; kc < 4; kc++) {
            pack_split(s[kc*2][0],   s[kc*2][1],   ph[kc][0], pl[kc][0]);
            pack_split(s[kc*2][2],   s[kc*2][3],   ph[kc][1], pl[kc][1]);
            pack_split(s[kc*2+1][0], s[kc*2+1][1], ph[kc][2], pl[kc][2]);
            pack_split(s[kc*2+1][2], s[kc*2+1][3], ph[kc][3], pl[kc][3]);
        }

#pragma unroll
        for (int kc = 0; kc < 4; kc++) {
            uint32_t vh[4][4], vl[4][4];
#pragma unroll
            for (int p = 0; p < 4; p++) {
                int row = kc * 16 + (v_g & 1) * 8 + v_r;
                int chunk = p * 2 + (v_g >> 1);
                uint32_t vd = sb + 2 * ATILE + asw(row, chunk);
                ldmx4t(vh[p], vd);
                ldmx4t(vl[p], vd + ATILE);
            }
#pragma unroll
            for (int p = 0; p < 4; p++)
#pragma unroll
                for (int h = 0; h < 2; h++) {
                    float* c = o[p * 2 + h];
                    mma16816(c, ph[kc], vh[p][h * 2], vh[p][h * 2 + 1]);
                    mma16816(c, ph[kc], vl[p][h * 2], vl[p][h * 2 + 1]);
                    mma16816(c, pl[kc], vh[p][h * 2], vh[p][h * 2 + 1]);
                }
        }
        __syncthreads();
    }

    l0 += __shfl_xor_sync(0xffffffffu, l0, 1);
    l0 += __shfl_xor_sync(0xffffffffu, l0, 2);
    l1 += __shfl_xor_sync(0xffffffffu, l1, 1);
    l1 += __shfl_xor_sync(0xffffffffu, l1, 2);
    const float inv0 = 1.f / l0;
    const float inv1 = 1.f / l1;

    const int b = bh >> 4, h = bh & 15;
    const int t0 = q0 + r0;
    size_t base0 = ((size_t)(b * TT + t0)) * DD + h * HD;
    size_t base1 = base0 + (size_t)8 * DD;
#pragma unroll
    for (int nt = 0; nt < 8; nt++) {
        const int col = nt * 8 + (lane & 3) * 2;
        *(uint32_t*)(Ohi + base0 + col) = pack_h(o[nt][0] * inv0, o[nt][1] * inv0);
        *(uint32_t*)(Ohi + base1 + col) = pack_h(o[nt][2] * inv1, o[nt][3] * inv1);
    }
}

// ---------------------------------------------------------------------------
// kernel_launch
// ---------------------------------------------------------------------------
extern "C" void kernel_launch(void* const* d_in, const int* in_sizes, int n_in,
                              void* d_out, int out_size)
{
    (void)in_sizes; (void)n_in; (void)out_size;
    const float* x  = (const float*)d_in[0];
    const float* Wq = (const float*)d_in[1];
    const float* Wk = (const float*)d_in[2];
    const float* Wv = (const float*)d_in[3];
    const float* Wo = (const float*)d_in[4];
    const float* Wf = (const float*)d_in[5];
    const float* bf = (const float*)d_in[6];
    float* out = (float*)d_out;

    float* cp;
    cudaGetSymbolAddress((void**)&cp, g_c);

    __half *xhi, *xlo, *ohi;
    __half *qhi, *qlo, *khi, *klo, *vhi, *vlo;
    __half *wqh, *wkh, *wvh, *woh, *wfth, *wftl;
    cudaGetSymbolAddress((void**)&xhi, g_xhi);
    cudaGetSymbolAddress((void**)&xlo, g_xlo);
    cudaGetSymbolAddress((void**)&ohi, g_ohi);
    cudaGetSymbolAddress((void**)&qhi, g_qhi);
    cudaGetSymbolAddress((void**)&qlo, g_qlo);
    cudaGetSymbolAddress((void**)&khi, g_khi);
    cudaGetSymbolAddress((void**)&klo, g_klo);
    cudaGetSymbolAddress((void**)&vhi, g_vhi);
    cudaGetSymbolAddress((void**)&vlo, g_vlo);
    cudaGetSymbolAddress((void**)&wqh, g_wqh);
    cudaGetSymbolAddress((void**)&wkh, g_wkh);
    cudaGetSymbolAddress((void**)&wvh, g_wvh);
    cudaGetSymbolAddress((void**)&woh, g_woh);
    cudaGetSymbolAddress((void**)&wfth, g_wfth);
    cudaGetSymbolAddress((void**)&wftl, g_wftl);

    cudaFuncSetAttribute(gemm_qkv_forget,
                         cudaFuncAttributeMaxDynamicSharedMemorySize, GEMM_SMEM);
    cudaFuncSetAttribute(gemm_out,
                         cudaFuncAttributeMaxDynamicSharedMemorySize, GEMM_SMEM);
    cudaFuncSetAttribute(attn_mma,
                         cudaFuncAttributeMaxDynamicSharedMemorySize, ATTN_SMEM);

    prep_kernel<<<8256, 256>>>(x, Wq, Wk, Wv, Wo, Wf,
                               xhi, xlo, wqh, wkh, wvh, woh, wfth, wftl);

    gemm_qkv_forget<<<dim3(25, 32), 128, GEMM_SMEM>>>(
        xhi, xlo, wqh, wkh, wvh, wfth, wftl, bf, cp,
        qhi, qlo, khi, klo, vhi, vlo);

    cumsum_kernel<<<BB * HH, 256>>>(cp);

    attn_mma<<<dim3(TT / 128, BB * HH), 256, ATTN_SMEM>>>(
        qhi, qlo, khi, klo, vhi, vlo, cp, ohi);

    gemm_out<<<dim3(DD / 128, MM / 128), 128, GEMM_SMEM>>>(
        ohi, woh, out);
}

// round 16
// speedup vs baseline: 1.1063x; 1.1063x over previous
#include <cuda_runtime.h>
#include <cuda_fp16.h>
#include <math.h>
#include <stdint.h>

// Problem constants
#define BB 2
#define TT 2048
#define DD 1024
#define HH 16
#define HD 64
#define MM (BB*TT)   // 4096

// ---------------------------------------------------------------------------
// Scratch (device globals; no allocation allowed)
// ---------------------------------------------------------------------------
__device__ float g_c[BB*HH*TT];

__device__ __half g_xhi[MM*DD], g_xlo[MM*DD];
__device__ __half g_qhi[MM*DD], g_qlo[MM*DD];        // [B,H,T,HD] (qlo unused by attn)
__device__ __half g_khi[MM*DD], g_klo[MM*DD];
__device__ __half g_vhi[MM*DD], g_vlo[MM*DD];
__device__ __half g_ohi[MM*DD];
__device__ __half g_wqh[DD*DD];
__device__ __half g_wkh[DD*DD];
__device__ __half g_wvh[DD*DD];
__device__ __half g_woh[DD*DD];
__device__ __half g_wfth[HH*DD], g_wftl[HH*DD];

// ---------------------------------------------------------------------------
// PTX helpers
// ---------------------------------------------------------------------------
__device__ __forceinline__ uint32_t smem_u32(const void* p) {
    uint32_t a;
    asm("{ .reg .u64 t; cvta.to.shared.u64 t, %1; cvt.u32.u64 %0, t; }"
        : "=r"(a) : "l"(p));
    return a;
}
__device__ __forceinline__ void cp16(uint32_t dst, const void* src) {
    asm volatile("cp.async.cg.shared.global [%0], [%1], 16;"
                 :: "r"(dst), "l"(src) : "memory");
}
__device__ __forceinline__ void cp_commit() {
    asm volatile("cp.async.commit_group;" ::: "memory");
}
template<int N> __device__ __forceinline__ void cp_wait() {
    asm volatile("cp.async.wait_group %0;" :: "n"(N) : "memory");
}
__device__ __forceinline__ void ldmx4(uint32_t* r, uint32_t addr) {
    asm volatile("ldmatrix.sync.aligned.m8n8.x4.shared.b16 {%0,%1,%2,%3}, [%4];"
                 : "=r"(r[0]), "=r"(r[1]), "=r"(r[2]), "=r"(r[3]) : "r"(addr));
}
__device__ __forceinline__ void ldmx4t(uint32_t* r, uint32_t addr) {
    asm volatile("ldmatrix.sync.aligned.m8n8.x4.trans.shared.b16 {%0,%1,%2,%3}, [%4];"
                 : "=r"(r[0]), "=r"(r[1]), "=r"(r[2]), "=r"(r[3]) : "r"(addr));
}
__device__ __forceinline__ void mma16816(float* c, const uint32_t* a,
                                         uint32_t b0, uint32_t b1) {
    asm volatile(
        "mma.sync.aligned.m16n8k16.row.col.f32.f16.f16.f32 "
        "{%0,%1,%2,%3}, {%4,%5,%6,%7}, {%8,%9}, {%0,%1,%2,%3};"
        : "+f"(c[0]), "+f"(c[1]), "+f"(c[2]), "+f"(c[3])
        : "r"(a[0]), "r"(a[1]), "r"(a[2]), "r"(a[3]), "r"(b0), "r"(b1));
}
__device__ __forceinline__ float ex2f(float x) {
    float r;
    asm("ex2.approx.ftz.f32 %0, %1;" : "=f"(r) : "f"(x));
    return r;
}
__device__ __forceinline__ void pack_split(float a, float b,
                                           uint32_t& hi, uint32_t& lo) {
    __half ha = __float2half_rn(a);
    __half hb = __float2half_rn(b);
    __half la = __float2half_rn(a - __half2float(ha));
    __half lb = __float2half_rn(b - __half2float(hb));
    __half2 H = __halves2half2(ha, hb);
    __half2 L = __halves2half2(la, lb);
    hi = *reinterpret_cast<uint32_t*>(&H);
    lo = *reinterpret_cast<uint32_t*>(&L);
}
__device__ __forceinline__ uint32_t pack_h(float a, float b) {
    __half2 H = __halves2half2(__float2half_rn(a), __float2half_rn(b));
    return *reinterpret_cast<uint32_t*>(&H);
}

#define LOG2E 1.44269504088896340736f

__device__ __forceinline__ uint32_t asw(int row, int chunk) {
    return (uint32_t)(row * 128 + ((chunk ^ (row & 7)) * 16));
}

// ---------------------------------------------------------------------------
// Fused preprocessing
// ---------------------------------------------------------------------------
__global__ __launch_bounds__(256) void prep_kernel(
    const float* __restrict__ x,
    const float* __restrict__ W0, const float* __restrict__ W1,
    const float* __restrict__ W2, const float* __restrict__ W3,
    const float* __restrict__ Wf,
    __half* __restrict__ xhi, __half* __restrict__ xlo,
    __half* __restrict__ H0, __half* __restrict__ H1,
    __half* __restrict__ H2, __half* __restrict__ H3,
    __half* __restrict__ Th, __half* __restrict__ Tl)
{
    __shared__ float t[32][33];
    const int bid = blockIdx.x;
    const int tid = threadIdx.x;

    if (bid < 4096) {
        int i = bid * 256 + tid;
        float4 v = ((const float4*)x)[i];
        uint32_t h0, l0, h1, l1;
        pack_split(v.x, v.y, h0, l0);
        pack_split(v.z, v.w, h1, l1);
        ((uint32_t*)xhi)[2*i]   = h0;
        ((uint32_t*)xhi)[2*i+1] = h1;
        ((uint32_t*)xlo)[2*i]   = l0;
        ((uint32_t*)xlo)[2*i+1] = l1;
    } else if (bid < 8192) {
        const int inner = bid - 4096;
        const int z = inner >> 10;
        const int rem = inner & 1023;
        const int bx = (rem & 31) * 32;
        const int by = (rem >> 5) * 32;
        const float* W  = (z == 0) ? W0 : (z == 1) ? W1 : (z == 2) ? W2 : W3;
        __half* Whi     = (z == 0) ? H0 : (z == 1) ? H1 : (z == 2) ? H2 : H3;
        const int tx = tid & 31, ty = tid >> 5;
#pragma unroll
        for (int j = 0; j < 32; j += 8)
            t[ty + j][tx] = W[(size_t)(by + ty + j) * DD + bx + tx];
        __syncthreads();
#pragma unroll
        for (int j = 0; j < 32; j += 8) {
            float v = t[tx][ty + j];
            Whi[(size_t)(bx + ty + j) * DD + by + tx] = __float2half_rn(v);
        }
    } else {
        int idx = (bid - 8192) * 256 + tid;
        int h = idx >> 10;
        int d = idx & 1023;
        float v = Wf[d * HH + h];
        __half hi = __float2half_rn(v);
        __half lo = __float2half_rn(v - __half2float(hi));
        Th[h * DD + d] = hi;
        Tl[h * DD + d] = lo;
    }
}

// ---------------------------------------------------------------------------
// Big GEMM core (unchanged)
// ---------------------------------------------------------------------------
#define GT     16384
#define GSTG   (2*GT)
#define GEMM_SMEM (3*GSTG)   // 98304
#define EPIT   (128*272)

template<typename EPILOG>
__device__ __forceinline__ void gemm1p_body(
    uint32_t smb, char* smraw, int tid,
    const __half* a_h, const __half* b_h,
    EPILOG epi)
{
    const int wid  = tid >> 5;
    const int lane = tid & 31;
    const int wm = (wid & 1) * 64;
    const int wn = (wid >> 1) * 64;

    float acc[4][8][4];
#pragma unroll
    for (int i = 0; i < 4; i++)
#pragma unroll
        for (int j = 0; j < 8; j++)
#pragma unroll
            for (int k = 0; k < 4; k++) acc[i][j][k] = 0.f;

    const int a_row = lane & 15;
    const int a_chk = lane >> 4;
    const int b_mat = lane >> 3;
    const int b_row = (b_mat >> 1) * 8 + (lane & 7);
    const int b_chk = b_mat & 1;

    auto stage = [&](uint32_t sbase, int k0) {
        const __half* bases[2] = { a_h + k0, b_h + k0 };
#pragma unroll
        for (int mat = 0; mat < 2; mat++) {
#pragma unroll
            for (int i = 0; i < 8; i++) {
                int s = tid + i * 128;
                int row = s >> 3, c = s & 7;
                cp16(sbase + mat * GT + asw(row, c),
                     bases[mat] + (size_t)row * DD + c * 8);
            }
        }
    };

    stage(smb, 0);
    cp_commit();
    stage(smb + GSTG, 64);
    cp_commit();

    for (int it = 0; it < 16; it++) {
        if (it + 2 < 16) cp_wait<1>(); else cp_wait<0>();
        __syncthreads();
        if (it + 2 < 16) {
            stage(smb + ((it + 2) % 3) * GSTG, (it + 2) * 64);
            cp_commit();
        }

        const uint32_t sb = smb + (it % 3) * GSTG;
#pragma unroll
        for (int ks = 0; ks < 4; ks++) {
            uint32_t af[4][4], bf[4][4];
#pragma unroll
            for (int mt = 0; mt < 4; mt++)
                ldmx4(af[mt], sb + asw(wm + mt * 16 + a_row, ks * 2 + a_chk));
#pragma unroll
            for (int ng = 0; ng < 4; ng++)
                ldmx4(bf[ng], sb + GT + asw(wn + ng * 16 + b_row, ks * 2 + b_chk));
#pragma unroll
            for (int mt = 0; mt < 4; mt++)
#pragma unroll
                for (int ng = 0; ng < 4; ng++)
#pragma unroll
                    for (int h = 0; h < 2; h++)
                        mma16816(acc[mt][ng * 2 + h], af[mt],
                                 bf[ng][h * 2], bf[ng][h * 2 + 1]);
        }
    }

    epi(acc, wm, wn, lane, wid);
}

// ---------------------------------------------------------------------------
// Forget-gate device path (unchanged)
// ---------------------------------------------------------------------------
#define FG_XL   16384
#define FG_WH   32768
#define FG_WL   34816
#define FG_STG  36864

__device__ void forget_body(
    char* smraw, uint32_t smb, int tid, int m0,
    const __half* __restrict__ xhi, const __half* __restrict__ xlo,
    const __half* __restrict__ wfh, const __half* __restrict__ wfl,
    const float* __restrict__ bf, float* __restrict__ lf)
{
    const int wid  = tid >> 5;
    const int lane = tid & 31;
    const int wm = wid * 32;

    const __half* xh_ = xhi + (size_t)m0 * DD;
    const __half* xl_ = xlo + (size_t)m0 * DD;

    float acc[2][2][4];
#pragma unroll
    for (int i = 0; i < 2; i++)
#pragma unroll
        for (int j = 0; j < 2; j++)
#pragma unroll
            for (int k = 0; k < 4; k++) acc[i][j][k] = 0.f;

    const int a_row = lane & 15;
    const int a_chk = lane >> 4;
    const int b_mat = lane >> 3;
    const int b_row = (b_mat >> 1) * 8 + (lane & 7);
    const int b_chk = b_mat & 1;

    auto stage = [&](uint32_t sbase, int k0) {
#pragma unroll
        for (int i = 0; i < 8; i++) {
            int s = tid + i * 128;
            int row = s >> 3, c = s & 7;
            cp16(sbase + asw(row, c),         xh_ + (size_t)row * DD + k0 + c * 8);
            cp16(sbase + FG_XL + asw(row, c), xl_ + (size_t)row * DD + k0 + c * 8);
        }
        {
            int row = tid >> 3, c = tid & 7;
            cp16(sbase + FG_WH + asw(row, c), wfh + (size_t)row * DD + k0 + c * 8);
            cp16(sbase + FG_WL + asw(row, c), wfl + (size_t)row * DD + k0 + c * 8);
        }
    };

    stage(smb, 0);
    cp_commit();

    for (int it = 0; it < 16; it++) {
        if (it + 1 < 16) {
            stage(smb + ((it + 1) & 1) * FG_STG, (it + 1) * 64);
            cp_commit();
            cp_wait<1>();
        } else {
            cp_wait<0>();
        }
        __syncthreads();

        const uint32_t sb = smb + (it & 1) * FG_STG;
#pragma unroll
        for (int ks = 0; ks < 4; ks++) {
            uint32_t ah[2][4], al[2][4], bh[4], bl[4];
#pragma unroll
            for (int mt = 0; mt < 2; mt++) {
                uint32_t aoff = asw(wm + mt * 16 + a_row, ks * 2 + a_chk);
                ldmx4(ah[mt], sb + aoff);
                ldmx4(al[mt], sb + FG_XL + aoff);
            }
            {
                uint32_t boff = asw(b_row, ks * 2 + b_chk);
                ldmx4(bh, sb + FG_WH + boff);
                ldmx4(bl, sb + FG_WL + boff);
            }
#pragma unroll
            for (int mt = 0; mt < 2; mt++)
#pragma unroll
                for (int h = 0; h < 2; h++) {
                    float* c = acc[mt][h];
                    mma16816(c, ah[mt], bh[h * 2], bh[h * 2 + 1]);
                    mma16816(c, ah[mt], bl[h * 2], bl[h * 2 + 1]);
                    mma16816(c, al[mt], bh[h * 2], bh[h * 2 + 1]);
                }
        }
        __syncthreads();
    }

    const int r0 = lane >> 2;
    const int cpair = (lane & 3) * 2;
#pragma unroll
    for (int mt = 0; mt < 2; mt++) {
#pragma unroll
        for (int nt = 0; nt < 2; nt++) {
            const int h0 = nt * 8 + cpair;
            const float bf0 = bf[h0], bf1 = bf[h0 + 1];
#pragma unroll
            for (int half = 0; half < 2; half++) {
                const int m = m0 + wm + mt * 16 + r0 + half * 8;
                const int b = m >> 11;
                const int t = m & (TT - 1);
                float z0 = acc[mt][nt][half * 2]     + bf0;
                float z1 = acc[mt][nt][half * 2 + 1] + bf1;
                float ls0 = (z0 >= 0.f) ? -log1pf(__expf(-z0))
                                        : z0 - log1pf(__expf(z0));
                float ls1 = (z1 >= 0.f) ? -log1pf(__expf(-z1))
                                        : z1 - log1pf(__expf(z1));
                ls0 = fminf(fmaxf(ls0, -10.f), 0.f);
                ls1 = fminf(fmaxf(ls1, -10.f), 0.f);
                lf[(size_t)(b * HH + h0)     * TT + t] = ls0;
                lf[(size_t)(b * HH + h0 + 1) * TT + t] = ls1;
            }
        }
    }
}

// ---------------------------------------------------------------------------
// Union kernel: QKV GEMM (blockIdx.x < 24) + forget gate (blockIdx.x == 24).
// ---------------------------------------------------------------------------
__global__ __launch_bounds__(128, 2) void gemm_qkv_forget(
    const __half* __restrict__ xh, const __half* __restrict__ xlo,
    const __half* __restrict__ wqh, const __half* __restrict__ wkh,
    const __half* __restrict__ wvh,
    const __half* __restrict__ wfh, const __half* __restrict__ wfl,
    const float* __restrict__ bf, float* __restrict__ lf,
    __half* __restrict__ qhi, __half* __restrict__ qlo,
    __half* __restrict__ khi, __half* __restrict__ klo,
    __half* __restrict__ vhi, __half* __restrict__ vlo)
{
    extern __shared__ char smraw[];
    const uint32_t smb = smem_u32(smraw);
    const int tid = threadIdx.x;

    if (blockIdx.x == 24) {
        forget_body(smraw, smb, tid, blockIdx.y * 128,
                    xh, xlo, wfh, wfl, bf, lf);
        return;
    }

    const int nmat = blockIdx.x >> 3;
    const int nloc = (blockIdx.x & 7) * 128;
    const int m0 = blockIdx.y * 128;

    const __half* a_h = xh + (size_t)m0 * DD;
    const __half* b_h = ((nmat == 0) ? wqh : (nmat == 1) ? wkh : wvh)
                        + (size_t)nloc * DD;
    __half* Chi = (nmat == 0) ? qhi : (nmat == 1) ? khi : vhi;
    __half* Clo = (nmat == 0) ? qlo : (nmat == 1) ? klo : vlo;

    gemm1p_body(smb, smraw, tid, a_h, b_h,
        [&](float acc[4][8][4], int wm, int wn, int lane, int wid) {
            __syncthreads();
            char* Sh = smraw;
            char* Sl = smraw + EPIT;
            const int r0 = lane >> 2;
            const int cpair = (lane & 3) * 2;
#pragma unroll
            for (int mt = 0; mt < 4; mt++) {
#pragma unroll
                for (int nt = 0; nt < 8; nt++) {
                    const int row0 = wm + mt * 16 + r0;
                    const int col  = wn + nt * 8 + cpair;
                    uint32_t h0, l0, h1, l1;
                    pack_split(acc[mt][nt][0], acc[mt][nt][1], h0, l0);
                    pack_split(acc[mt][nt][2], acc[mt][nt][3], h1, l1);
                    *(uint32_t*)(Sh + row0 * 272 + col * 2) = h0;
                    *(uint32_t*)(Sl + row0 * 272 + col * 2) = l0;
                    *(uint32_t*)(Sh + (row0 + 8) * 272 + col * 2) = h1;
                    *(uint32_t*)(Sl + (row0 + 8) * 272 + col * 2) = l1;
                }
            }
            __syncthreads();

            const int g  = lane >> 3;
            const int ck = lane & 7;
#pragma unroll
            for (int p = 0; p < 32; p++) {
                int flat = p * 16 + wid * 4 + g;
                int hl  = flat >> 8;
                int rem = flat & 255;
                int hh  = rem >> 7;
                int mm  = rem & 127;
                uint4 v = *(uint4*)(smraw + hl * EPIT + mm * 272
                                    + hh * 128 + ck * 16);
                const int m = m0 + mm;
                const int b = m >> 11;
                const int t = m & (TT - 1);
                const int h = (nloc >> 6) + hh;
                __half* dst = (hl == 0 ? Chi : Clo)
                            + (((size_t)((b * HH + h) * TT + t)) << 6) + ck * 8;
                *(uint4*)dst = v;
            }
        });
}

// ---------------------------------------------------------------------------
// Output GEMM
// ---------------------------------------------------------------------------
__global__ __launch_bounds__(128, 2) void gemm_out(
    const __half* __restrict__ Ah,
    const __half* __restrict__ Bhi,
    float* __restrict__ Cf)
{
    extern __shared__ char smraw[];
    const uint32_t smb = smem_u32(smraw);
    const int tid = threadIdx.x;
    const int n0 = blockIdx.x * 128;
    const int m0 = blockIdx.y * 128;

    const __half* a_h = Ah + (size_t)m0 * DD;
    const __half* b_h = Bhi + (size_t)n0 * DD;

    gemm1p_body(smb, smraw, tid, a_h, b_h,
        [&](float acc[4][8][4], int wm, int wn, int lane, int wid) {
            (void)wid;
            const int r0 = lane >> 2;
            const int cpair = (lane & 3) * 2;
#pragma unroll
            for (int mt = 0; mt < 4; mt++) {
#pragma unroll
                for (int nt = 0; nt < 8; nt++) {
                    const int m = m0 + wm + mt * 16 + r0;
                    const int n = n0 + wn + nt * 8 + cpair;
                    float* dst0 = Cf + (size_t)m * DD + n;
                    float* dst1 = Cf + (size_t)(m + 8) * DD + n;
                    *(float2*)dst0 = make_float2(acc[mt][nt][0], acc[mt][nt][1]);
                    *(float2*)dst1 = make_float2(acc[mt][nt][2], acc[mt][nt][3]);
                }
            }
        });
}

// ---------------------------------------------------------------------------
// Cumsum over T per (b,h)
// ---------------------------------------------------------------------------
__global__ __launch_bounds__(256) void cumsum_kernel(float* __restrict__ lf)
{
    const int bh = blockIdx.x;
    float* p = lf + (size_t)bh * TT;
    const int tid = threadIdx.x;
    const int lane = tid & 31, wid = tid >> 5;
    __shared__ float wsum[8];

    float v[8];
    float s = 0.f;
#pragma unroll
    for (int i = 0; i < 8; i++) { v[i] = p[tid * 8 + i]; s += v[i]; }

    float ss = s;
#pragma unroll
    for (int off = 1; off < 32; off <<= 1) {
        float n = __shfl_up_sync(0xffffffffu, ss, off);
        if (lane >= off) ss += n;
    }
    if (lane == 31) wsum[wid] = ss;
    __syncthreads();
    float woff = 0.f;
#pragma unroll
    for (int w = 0; w < 8; w++)
        if (w < wid) woff += wsum[w];

    float run = woff + ss - s;
#pragma unroll
    for (int i = 0; i < 8; i++) { run += v[i]; p[tid * 8 + i] = run; }
}

// ---------------------------------------------------------------------------
// HMMA forgetting attention: 64 q-rows/block (R14 geometry), Q single fp16.
// QK^T = qh*(kh+kl)  (2-product); PV stays 3-product.
// ---------------------------------------------------------------------------
#define ATILE  8192
#define ACKS   (4*ATILE)
#define ASTAGE (4*ATILE + 256)
#define AQOFF  (2*ASTAGE)
#define ATTN_SMEM (2*ASTAGE + ATILE)    // 74240 (Q hi only)

__device__ __forceinline__ void attn_stage(
    uint32_t sb,
    const __half* Kh, const __half* Kl,
    const __half* Vh, const __half* Vl,
    const float* cptr, int k0, int tid)
{
    const __half* mats[4] = {
        Kh + (size_t)k0 * HD, Kl + (size_t)k0 * HD,
        Vh + (size_t)k0 * HD, Vl + (size_t)k0 * HD };
#pragma unroll
    for (int mt = 0; mt < 4; mt++) {
#pragma unroll
        for (int i = 0; i < 4; i++) {
            int s = tid + i * 128;
            int row = s >> 3, c = s & 7;
            cp16(sb + mt * ATILE + asw(row, c), mats[mt] + row * HD + c * 8);
        }
    }
    if (tid < 16) cp16(sb + ACKS + tid * 16, cptr + k0 + tid * 4);
}

__global__ __launch_bounds__(128) void attn_mma(
    const __half* __restrict__ Qhi,
    const __half* __restrict__ Khi, const __half* __restrict__ Klo,
    const __half* __restrict__ Vhi, const __half* __restrict__ Vlo,
    const float* __restrict__ C,
    __half* __restrict__ Ohi)
{
    extern __shared__ char smraw[];
    const uint32_t smb = smem_u32(smraw);

    const int tid  = threadIdx.x;
    const int wid  = tid >> 5;
    const int lane = tid & 31;
    const int qt = blockIdx.x;
    const int bh = blockIdx.y;
    const int q0 = qt * 64;

    const __half* Qh = Qhi + (size_t)bh * TT * HD;
    const __half* Kh = Khi + (size_t)bh * TT * HD;
    const __half* Kl = Klo + (size_t)bh * TT * HD;
    const __half* Vh = Vhi + (size_t)bh * TT * HD;
    const __half* Vl = Vlo + (size_t)bh * TT * HD;
    const float* cptr = C + (size_t)bh * TT;

    int kt_start;
    {
        const float cq0v = cptr[q0];
        int lo = 0, hi = qt;
        while (lo < hi) {
            int mid = (lo + hi) >> 1;
            if (cq0v - cptr[mid * 64 + 63] >= -32.f) hi = mid;
            else lo = mid + 1;
        }
        kt_start = lo;
    }

    // group 0: Q hi tile only (512 cp16 / 128 thr = 4 each)
#pragma unroll
    for (int i = 0; i < 4; i++) {
        int s = tid + i * 128;
        int row = s >> 3, c = s & 7;
        cp16(smb + AQOFF + asw(row, c),
             Qh + (size_t)(q0 + row) * HD + c * 8);
    }
    cp_commit();
    // group 1: first K/V stage
    attn_stage(smb + (kt_start & 1) * ASTAGE, Kh, Kl, Vh, Vl, cptr,
               kt_start * 64, tid);
    cp_commit();

    cp_wait<1>();
    __syncthreads();

    const int a_row = lane & 15;
    const int a_chk = lane >> 4;
    uint32_t qh[4][4];
#pragma unroll
    for (int ks = 0; ks < 4; ks++)
        ldmx4(qh[ks], smb + AQOFF + asw(wid * 16 + a_row, ks * 2 + a_chk));

    const int r0 = wid * 16 + (lane >> 2);
    const float cq0 = cptr[q0 + r0];
    const float cq1 = cptr[q0 + r0 + 8];

    float m0 = -1e30f, m1 = -1e30f, l0 = 0.f, l1 = 0.f;
    float o[8][4];
#pragma unroll
    for (int i = 0; i < 8; i++)
#pragma unroll
        for (int j = 0; j < 4; j++) o[i][j] = 0.f;

    const int b_mat = lane >> 3;
    const int b_row = (b_mat >> 1) * 8 + (lane & 7);
    const int b_chk = b_mat & 1;
    const int v_g = lane >> 3;
    const int v_r = lane & 7;

    for (int kt = kt_start; kt <= qt; kt++) {
        if (kt < qt) {
            attn_stage(smb + ((kt + 1) & 1) * ASTAGE,
                       Kh, Kl, Vh, Vl, cptr, (kt + 1) * 64, tid);
            cp_commit();
            cp_wait<1>();
        } else {
            cp_wait<0>();
        }
        __syncthreads();

        const uint32_t sb = smb + (kt & 1) * ASTAGE;
        const float* cks = (const float*)(smraw + (kt & 1) * ASTAGE + ACKS);

        float s[8][4];
#pragma unroll
        for (int i = 0; i < 8; i++)
#pragma unroll
            for (int j = 0; j < 4; j++) s[i][j] = 0.f;

#pragma unroll
        for (int ks = 0; ks < 4; ks++) {
            uint32_t kh[4][4], kl[4][4];
#pragma unroll
            for (int ng = 0; ng < 4; ng++) {
                uint32_t bd = sb + asw(ng * 16 + b_row, ks * 2 + b_chk);
                ldmx4(kh[ng], bd);
                ldmx4(kl[ng], bd + ATILE);
            }
#pragma unroll
            for (int ng = 0; ng < 4; ng++)
#pragma unroll
                for (int h = 0; h < 2; h++) {
                    float* c = s[ng * 2 + h];
                    mma16816(c, qh[ks], kh[ng][h * 2], kh[ng][h * 2 + 1]);
                    mma16816(c, qh[ks], kl[ng][h * 2], kl[ng][h * 2 + 1]);
                }
        }

        const bool diag = (kt == qt);
        const int k0g = kt * 64;
#pragma unroll
        for (int nt = 0; nt < 8; nt++) {
            const int col = nt * 8 + (lane & 3) * 2;
            const float ck0 = cks[col], ck1 = cks[col + 1];
            float d00 = fmaxf(cq0 - ck0, -50.f);
            float d01 = fmaxf(cq0 - ck1, -50.f);
            float d10 = fmaxf(cq1 - ck0, -50.f);
            float d11 = fmaxf(cq1 - ck1, -50.f);
            s[nt][0] = fmaf(s[nt][0], 0.125f, d00);
            s[nt][1] = fmaf(s[nt][1], 0.125f, d01);
            s[nt][2] = fmaf(s[nt][2], 0.125f, d10);
            s[nt][3] = fmaf(s[nt][3], 0.125f, d11);
            if (diag) {
                if (k0g + col     > q0 + r0)     s[nt][0] = -1e30f;
                if (k0g + col + 1 > q0 + r0)     s[nt][1] = -1e30f;
                if (k0g + col     > q0 + r0 + 8) s[nt][2] = -1e30f;
                if (k0g + col + 1 > q0 + r0 + 8) s[nt][3] = -1e30f;
            }
        }

        float ml0 = -1e30f, ml1 = -1e30f;
#pragma unroll
        for (int nt = 0; nt < 8; nt++) {
            ml0 = fmaxf(ml0, fmaxf(s[nt][0], s[nt][1]));
            ml1 = fmaxf(ml1, fmaxf(s[nt][2], s[nt][3]));
        }
        ml0 = fmaxf(ml0, __shfl_xor_sync(0xffffffffu, ml0, 1));
        ml0 = fmaxf(ml0, __shfl_xor_sync(0xffffffffu, ml0, 2));
        ml1 = fmaxf(ml1, __shfl_xor_sync(0xffffffffu, ml1, 1));
        ml1 = fmaxf(ml1, __shfl_xor_sync(0xffffffffu, ml1, 2));
        const float mn0 = fmaxf(m0, ml0);
        const float mn1 = fmaxf(m1, ml1);
        const float corr0 = ex2f((m0 - mn0) * LOG2E);
        const float corr1 = ex2f((m1 - mn1) * LOG2E);
        m0 = mn0; m1 = mn1;

        float sum0 = 0.f, sum1 = 0.f;
#pragma unroll
        for (int nt = 0; nt < 8; nt++) {
            s[nt][0] = ex2f((s[nt][0] - mn0) * LOG2E);
            s[nt][1] = ex2f((s[nt][1] - mn0) * LOG2E);
            s[nt][2] = ex2f((s[nt][2] - mn1) * LOG2E);
            s[nt][3] = ex2f((s[nt][3] - mn1) * LOG2E);
            sum0 += s[nt][0] + s[nt][1];
            sum1 += s[nt][2] + s[nt][3];
        }
        l0 = l0 * corr0 + sum0;
        l1 = l1 * corr1 + sum1;
#pragma unroll
        for (int nt = 0; nt < 8; nt++) {
            o[nt][0] *= corr0; o[nt][1] *= corr0;
            o[nt][2] *= corr1; o[nt][3] *= corr1;
        }

        uint32_t ph[4][4], pl[4][4];
#pragma unroll
        for (int kc = 0; kc < 4; kc++) {
            pack_split(s[kc*2][0],   s[kc*2][1],   ph[kc][0], pl[kc][0]);
            pack_split(s[kc*2][2],   s[kc*2][3],   ph[kc][1], pl[kc][1]);
            pack_split(s[kc*2+1][0], s[kc*2+1][1], ph[kc][2], pl[kc][2]);
            pack_split(s[kc*2+1][2], s[kc*2+1][3], ph[kc][3], pl[kc][3]);
        }

#pragma unroll
        for (int kc = 0; kc < 4; kc++) {
            uint32_t vh[4][4], vl[4][4];
#pragma unroll
            for (int p = 0; p < 4; p++) {
                int row = kc * 16 + (v_g & 1) * 8 + v_r;
                int chunk = p * 2 + (v_g >> 1);
                uint32_t vd = sb + 2 * ATILE + asw(row, chunk);
                ldmx4t(vh[p], vd);
                ldmx4t(vl[p], vd + ATILE);
            }
#pragma unroll
            for (int p = 0; p < 4; p++)
#pragma unroll
                for (int h = 0; h < 2; h++) {
                    float* c = o[p * 2 + h];
                    mma16816(c, ph[kc], vh[p][h * 2], vh[p][h * 2 + 1]);
                    mma16816(c, ph[kc], vl[p][h * 2], vl[p][h * 2 + 1]);
                    mma16816(c, pl[kc], vh[p][h * 2], vh[p][h * 2 + 1]);
                }
        }
        __syncthreads();
    }

    l0 += __shfl_xor_sync(0xffffffffu, l0, 1);
    l0 += __shfl_xor_sync(0xffffffffu, l0, 2);
    l1 += __shfl_xor_sync(0xffffffffu, l1, 1);
    l1 += __shfl_xor_sync(0xffffffffu, l1, 2);
    const float inv0 = 1.f / l0;
    const float inv1 = 1.f / l1;

    const int b = bh >> 4, h = bh & 15;
    const int t0 = q0 + r0;
    size_t base0 = ((size_t)(b * TT + t0)) * DD + h * HD;
    size_t base1 = base0 + (size_t)8 * DD;
#pragma unroll
    for (int nt = 0; nt < 8; nt++) {
        const int col = nt * 8 + (lane & 3) * 2;
        *(uint32_t*)(Ohi + base0 + col) = pack_h(o[nt][0] * inv0, o[nt][1] * inv0);
        *(uint32_t*)(Ohi + base1 + col) = pack_h(o[nt][2] * inv1, o[nt][3] * inv1);
    }
}

// ---------------------------------------------------------------------------
// kernel_launch
// ---------------------------------------------------------------------------
extern "C" void kernel_launch(void* const* d_in, const int* in_sizes, int n_in,
                              void* d_out, int out_size)
{
    (void)in_sizes; (void)n_in; (void)out_size;
    const float* x  = (const float*)d_in[0];
    const float* Wq = (const float*)d_in[1];
    const float* Wk = (const float*)d_in[2];
    const float* Wv = (const float*)d_in[3];
    const float* Wo = (const float*)d_in[4];
    const float* Wf = (const float*)d_in[5];
    const float* bf = (const float*)d_in[6];
    float* out = (float*)d_out;

    float* cp;
    cudaGetSymbolAddress((void**)&cp, g_c);

    __half *xhi, *xlo, *ohi;
    __half *qhi, *qlo, *khi, *klo, *vhi, *vlo;
    __half *wqh, *wkh, *wvh, *woh, *wfth, *wftl;
    cudaGetSymbolAddress((void**)&xhi, g_xhi);
    cudaGetSymbolAddress((void**)&xlo, g_xlo);
    cudaGetSymbolAddress((void**)&ohi, g_ohi);
    cudaGetSymbolAddress((void**)&qhi, g_qhi);
    cudaGetSymbolAddress((void**)&qlo, g_qlo);
    cudaGetSymbolAddress((void**)&khi, g_khi);
    cudaGetSymbolAddress((void**)&klo, g_klo);
    cudaGetSymbolAddress((void**)&vhi, g_vhi);
    cudaGetSymbolAddress((void**)&vlo, g_vlo);
    cudaGetSymbolAddress((void**)&wqh, g_wqh);
    cudaGetSymbolAddress((void**)&wkh, g_wkh);
    cudaGetSymbolAddress((void**)&wvh, g_wvh);
    cudaGetSymbolAddress((void**)&woh, g_woh);
    cudaGetSymbolAddress((void**)&wfth, g_wfth);
    cudaGetSymbolAddress((void**)&wftl, g_wftl);

    cudaFuncSetAttribute(gemm_qkv_forget,
                         cudaFuncAttributeMaxDynamicSharedMemorySize, GEMM_SMEM);
    cudaFuncSetAttribute(gemm_out,
                         cudaFuncAttributeMaxDynamicSharedMemorySize, GEMM_SMEM);
    cudaFuncSetAttribute(attn_mma,
                         cudaFuncAttributeMaxDynamicSharedMemorySize, ATTN_SMEM);

    prep_kernel<<<8256, 256>>>(x, Wq, Wk, Wv, Wo, Wf,
                               xhi, xlo, wqh, wkh, wvh, woh, wfth, wftl);

    gemm_qkv_forget<<<dim3(25, 32), 128, GEMM_SMEM>>>(
        xhi, xlo, wqh, wkh, wvh, wfth, wftl, bf, cp,
        qhi, qlo, khi, klo, vhi, vlo);

    cumsum_kernel<<<BB * HH, 256>>>(cp);

    attn_mma<<<dim3(TT / 64, BB * HH), 128, ATTN_SMEM>>>(
        qhi, khi, klo, vhi, vlo, cp, ohi);

    gemm_out<<<dim3(DD / 128, MM / 128), 128, GEMM_SMEM>>>(
        ohi, woh, out);
}

// round 17
// speedup vs baseline: 1.2232x; 1.1057x over previous
#include <cuda_runtime.h>
#include <cuda_fp16.h>
#include <math.h>
#include <stdint.h>

// Problem constants
#define BB 2
#define TT 2048
#define DD 1024
#define HH 16
#define HD 64
#define MM (BB*TT)   // 4096

// ---------------------------------------------------------------------------
// Scratch (device globals; no allocation allowed)
// ---------------------------------------------------------------------------
__device__ float g_c[BB*HH*TT];

__device__ __half g_xhi[MM*DD], g_xlo[MM*DD];
__device__ __half g_qhi[MM*DD];                      // [B,H,T,HD] single fp16
__device__ __half g_khi[MM*DD];
__device__ __half g_vhi[MM*DD];
__device__ __half g_ohi[MM*DD];
__device__ __half g_wqh[DD*DD];
__device__ __half g_wkh[DD*DD];
__device__ __half g_wvh[DD*DD];
__device__ __half g_woh[DD*DD];
__device__ __half g_wfth[HH*DD], g_wftl[HH*DD];

// ---------------------------------------------------------------------------
// PTX helpers
// ---------------------------------------------------------------------------
__device__ __forceinline__ uint32_t smem_u32(const void* p) {
    uint32_t a;
    asm("{ .reg .u64 t; cvta.to.shared.u64 t, %1; cvt.u32.u64 %0, t; }"
        : "=r"(a) : "l"(p));
    return a;
}
__device__ __forceinline__ void cp16(uint32_t dst, const void* src) {
    asm volatile("cp.async.cg.shared.global [%0], [%1], 16;"
                 :: "r"(dst), "l"(src) : "memory");
}
__device__ __forceinline__ void cp_commit() {
    asm volatile("cp.async.commit_group;" ::: "memory");
}
template<int N> __device__ __forceinline__ void cp_wait() {
    asm volatile("cp.async.wait_group %0;" :: "n"(N) : "memory");
}
__device__ __forceinline__ void ldmx4(uint32_t* r, uint32_t addr) {
    asm volatile("ldmatrix.sync.aligned.m8n8.x4.shared.b16 {%0,%1,%2,%3}, [%4];"
                 : "=r"(r[0]), "=r"(r[1]), "=r"(r[2]), "=r"(r[3]) : "r"(addr));
}
__device__ __forceinline__ void ldmx4t(uint32_t* r, uint32_t addr) {
    asm volatile("ldmatrix.sync.aligned.m8n8.x4.trans.shared.b16 {%0,%1,%2,%3}, [%4];"
                 : "=r"(r[0]), "=r"(r[1]), "=r"(r[2]), "=r"(r[3]) : "r"(addr));
}
__device__ __forceinline__ void mma16816(float* c, const uint32_t* a,
                                         uint32_t b0, uint32_t b1) {
    asm volatile(
        "mma.sync.aligned.m16n8k16.row.col.f32.f16.f16.f32 "
        "{%0,%1,%2,%3}, {%4,%5,%6,%7}, {%8,%9}, {%0,%1,%2,%3};"
        : "+f"(c[0]), "+f"(c[1]), "+f"(c[2]), "+f"(c[3])
        : "r"(a[0]), "r"(a[1]), "r"(a[2]), "r"(a[3]), "r"(b0), "r"(b1));
}
__device__ __forceinline__ float ex2f(float x) {
    float r;
    asm("ex2.approx.ftz.f32 %0, %1;" : "=f"(r) : "f"(x));
    return r;
}
__device__ __forceinline__ void pack_split(float a, float b,
                                           uint32_t& hi, uint32_t& lo) {
    __half ha = __float2half_rn(a);
    __half hb = __float2half_rn(b);
    __half la = __float2half_rn(a - __half2float(ha));
    __half lb = __float2half_rn(b - __half2float(hb));
    __half2 H = __halves2half2(ha, hb);
    __half2 L = __halves2half2(la, lb);
    hi = *reinterpret_cast<uint32_t*>(&H);
    lo = *reinterpret_cast<uint32_t*>(&L);
}
__device__ __forceinline__ uint32_t pack_h(float a, float b) {
    __half2 H = __halves2half2(__float2half_rn(a), __float2half_rn(b));
    return *reinterpret_cast<uint32_t*>(&H);
}

#define LOG2E 1.44269504088896340736f

__device__ __forceinline__ uint32_t asw(int row, int chunk) {
    return (uint32_t)(row * 128 + ((chunk ^ (row & 7)) * 16));
}

// ---------------------------------------------------------------------------
// Fused preprocessing
// ---------------------------------------------------------------------------
__global__ __launch_bounds__(256) void prep_kernel(
    const float* __restrict__ x,
    const float* __restrict__ W0, const float* __restrict__ W1,
    const float* __restrict__ W2, const float* __restrict__ W3,
    const float* __restrict__ Wf,
    __half* __restrict__ xhi, __half* __restrict__ xlo,
    __half* __restrict__ H0, __half* __restrict__ H1,
    __half* __restrict__ H2, __half* __restrict__ H3,
    __half* __restrict__ Th, __half* __restrict__ Tl)
{
    __shared__ float t[32][33];
    const int bid = blockIdx.x;
    const int tid = threadIdx.x;

    if (bid < 4096) {
        int i = bid * 256 + tid;
        float4 v = ((const float4*)x)[i];
        uint32_t h0, l0, h1, l1;
        pack_split(v.x, v.y, h0, l0);
        pack_split(v.z, v.w, h1, l1);
        ((uint32_t*)xhi)[2*i]   = h0;
        ((uint32_t*)xhi)[2*i+1] = h1;
        ((uint32_t*)xlo)[2*i]   = l0;
        ((uint32_t*)xlo)[2*i+1] = l1;
    } else if (bid < 8192) {
        const int inner = bid - 4096;
        const int z = inner >> 10;
        const int rem = inner & 1023;
        const int bx = (rem & 31) * 32;
        const int by = (rem >> 5) * 32;
        const float* W  = (z == 0) ? W0 : (z == 1) ? W1 : (z == 2) ? W2 : W3;
        __half* Whi     = (z == 0) ? H0 : (z == 1) ? H1 : (z == 2) ? H2 : H3;
        const int tx = tid & 31, ty = tid >> 5;
#pragma unroll
        for (int j = 0; j < 32; j += 8)
            t[ty + j][tx] = W[(size_t)(by + ty + j) * DD + bx + tx];
        __syncthreads();
#pragma unroll
        for (int j = 0; j < 32; j += 8) {
            float v = t[tx][ty + j];
            Whi[(size_t)(bx + ty + j) * DD + by + tx] = __float2half_rn(v);
        }
    } else {
        int idx = (bid - 8192) * 256 + tid;
        int h = idx >> 10;
        int d = idx & 1023;
        float v = Wf[d * HH + h];
        __half hi = __float2half_rn(v);
        __half lo = __float2half_rn(v - __half2float(hi));
        Th[h * DD + d] = hi;
        Tl[h * DD + d] = lo;
    }
}

// ---------------------------------------------------------------------------
// Big GEMM core (unchanged)
// ---------------------------------------------------------------------------
#define GT     16384
#define GSTG   (2*GT)
#define GEMM_SMEM (3*GSTG)   // 98304
#define EPIT   (128*272)

template<typename EPILOG>
__device__ __forceinline__ void gemm1p_body(
    uint32_t smb, char* smraw, int tid,
    const __half* a_h, const __half* b_h,
    EPILOG epi)
{
    const int wid  = tid >> 5;
    const int lane = tid & 31;
    const int wm = (wid & 1) * 64;
    const int wn = (wid >> 1) * 64;

    float acc[4][8][4];
#pragma unroll
    for (int i = 0; i < 4; i++)
#pragma unroll
        for (int j = 0; j < 8; j++)
#pragma unroll
            for (int k = 0; k < 4; k++) acc[i][j][k] = 0.f;

    const int a_row = lane & 15;
    const int a_chk = lane >> 4;
    const int b_mat = lane >> 3;
    const int b_row = (b_mat >> 1) * 8 + (lane & 7);
    const int b_chk = b_mat & 1;

    auto stage = [&](uint32_t sbase, int k0) {
        const __half* bases[2] = { a_h + k0, b_h + k0 };
#pragma unroll
        for (int mat = 0; mat < 2; mat++) {
#pragma unroll
            for (int i = 0; i < 8; i++) {
                int s = tid + i * 128;
                int row = s >> 3, c = s & 7;
                cp16(sbase + mat * GT + asw(row, c),
                     bases[mat] + (size_t)row * DD + c * 8);
            }
        }
    };

    stage(smb, 0);
    cp_commit();
    stage(smb + GSTG, 64);
    cp_commit();

    for (int it = 0; it < 16; it++) {
        if (it + 2 < 16) cp_wait<1>(); else cp_wait<0>();
        __syncthreads();
        if (it + 2 < 16) {
            stage(smb + ((it + 2) % 3) * GSTG, (it + 2) * 64);
            cp_commit();
        }

        const uint32_t sb = smb + (it % 3) * GSTG;
#pragma unroll
        for (int ks = 0; ks < 4; ks++) {
            uint32_t af[4][4], bf[4][4];
#pragma unroll
            for (int mt = 0; mt < 4; mt++)
                ldmx4(af[mt], sb + asw(wm + mt * 16 + a_row, ks * 2 + a_chk));
#pragma unroll
            for (int ng = 0; ng < 4; ng++)
                ldmx4(bf[ng], sb + GT + asw(wn + ng * 16 + b_row, ks * 2 + b_chk));
#pragma unroll
            for (int mt = 0; mt < 4; mt++)
#pragma unroll
                for (int ng = 0; ng < 4; ng++)
#pragma unroll
                    for (int h = 0; h < 2; h++)
                        mma16816(acc[mt][ng * 2 + h], af[mt],
                                 bf[ng][h * 2], bf[ng][h * 2 + 1]);
        }
    }

    epi(acc, wm, wn, lane, wid);
}

// ---------------------------------------------------------------------------
// Forget-gate device path (unchanged)
// ---------------------------------------------------------------------------
#define FG_XL   16384
#define FG_WH   32768
#define FG_WL   34816
#define FG_STG  36864

__device__ void forget_body(
    char* smraw, uint32_t smb, int tid, int m0,
    const __half* __restrict__ xhi, const __half* __restrict__ xlo,
    const __half* __restrict__ wfh, const __half* __restrict__ wfl,
    const float* __restrict__ bf, float* __restrict__ lf)
{
    const int wid  = tid >> 5;
    const int lane = tid & 31;
    const int wm = wid * 32;

    const __half* xh_ = xhi + (size_t)m0 * DD;
    const __half* xl_ = xlo + (size_t)m0 * DD;

    float acc[2][2][4];
#pragma unroll
    for (int i = 0; i < 2; i++)
#pragma unroll
        for (int j = 0; j < 2; j++)
#pragma unroll
            for (int k = 0; k < 4; k++) acc[i][j][k] = 0.f;

    const int a_row = lane & 15;
    const int a_chk = lane >> 4;
    const int b_mat = lane >> 3;
    const int b_row = (b_mat >> 1) * 8 + (lane & 7);
    const int b_chk = b_mat & 1;

    auto stage = [&](uint32_t sbase, int k0) {
#pragma unroll
        for (int i = 0; i < 8; i++) {
            int s = tid + i * 128;
            int row = s >> 3, c = s & 7;
            cp16(sbase + asw(row, c),         xh_ + (size_t)row * DD + k0 + c * 8);
            cp16(sbase + FG_XL + asw(row, c), xl_ + (size_t)row * DD + k0 + c * 8);
        }
        {
            int row = tid >> 3, c = tid & 7;
            cp16(sbase + FG_WH + asw(row, c), wfh + (size_t)row * DD + k0 + c * 8);
            cp16(sbase + FG_WL + asw(row, c), wfl + (size_t)row * DD + k0 + c * 8);
        }
    };

    stage(smb, 0);
    cp_commit();

    for (int it = 0; it < 16; it++) {
        if (it + 1 < 16) {
            stage(smb + ((it + 1) & 1) * FG_STG, (it + 1) * 64);
            cp_commit();
            cp_wait<1>();
        } else {
            cp_wait<0>();
        }
        __syncthreads();

        const uint32_t sb = smb + (it & 1) * FG_STG;
#pragma unroll
        for (int ks = 0; ks < 4; ks++) {
            uint32_t ah[2][4], al[2][4], bh[4], bl[4];
#pragma unroll
            for (int mt = 0; mt < 2; mt++) {
                uint32_t aoff = asw(wm + mt * 16 + a_row, ks * 2 + a_chk);
                ldmx4(ah[mt], sb + aoff);
                ldmx4(al[mt], sb + FG_XL + aoff);
            }
            {
                uint32_t boff = asw(b_row, ks * 2 + b_chk);
                ldmx4(bh, sb + FG_WH + boff);
                ldmx4(bl, sb + FG_WL + boff);
            }
#pragma unroll
            for (int mt = 0; mt < 2; mt++)
#pragma unroll
                for (int h = 0; h < 2; h++) {
                    float* c = acc[mt][h];
                    mma16816(c, ah[mt], bh[h * 2], bh[h * 2 + 1]);
                    mma16816(c, ah[mt], bl[h * 2], bl[h * 2 + 1]);
                    mma16816(c, al[mt], bh[h * 2], bh[h * 2 + 1]);
                }
        }
        __syncthreads();
    }

    const int r0 = lane >> 2;
    const int cpair = (lane & 3) * 2;
#pragma unroll
    for (int mt = 0; mt < 2; mt++) {
#pragma unroll
        for (int nt = 0; nt < 2; nt++) {
            const int h0 = nt * 8 + cpair;
            const float bf0 = bf[h0], bf1 = bf[h0 + 1];
#pragma unroll
            for (int half = 0; half < 2; half++) {
                const int m = m0 + wm + mt * 16 + r0 + half * 8;
                const int b = m >> 11;
                const int t = m & (TT - 1);
                float z0 = acc[mt][nt][half * 2]     + bf0;
                float z1 = acc[mt][nt][half * 2 + 1] + bf1;
                float ls0 = (z0 >= 0.f) ? -log1pf(__expf(-z0))
                                        : z0 - log1pf(__expf(z0));
                float ls1 = (z1 >= 0.f) ? -log1pf(__expf(-z1))
                                        : z1 - log1pf(__expf(z1));
                ls0 = fminf(fmaxf(ls0, -10.f), 0.f);
                ls1 = fminf(fmaxf(ls1, -10.f), 0.f);
                lf[(size_t)(b * HH + h0)     * TT + t] = ls0;
                lf[(size_t)(b * HH + h0 + 1) * TT + t] = ls1;
            }
        }
    }
}

// ---------------------------------------------------------------------------
// Union kernel: QKV GEMM (hi-only outputs) + forget gate (blockIdx.x == 24).
// ---------------------------------------------------------------------------
__global__ __launch_bounds__(128, 2) void gemm_qkv_forget(
    const __half* __restrict__ xh, const __half* __restrict__ xlo,
    const __half* __restrict__ wqh, const __half* __restrict__ wkh,
    const __half* __restrict__ wvh,
    const __half* __restrict__ wfh, const __half* __restrict__ wfl,
    const float* __restrict__ bf, float* __restrict__ lf,
    __half* __restrict__ qhi, __half* __restrict__ khi,
    __half* __restrict__ vhi)
{
    extern __shared__ char smraw[];
    const uint32_t smb = smem_u32(smraw);
    const int tid = threadIdx.x;

    if (blockIdx.x == 24) {
        forget_body(smraw, smb, tid, blockIdx.y * 128,
                    xh, xlo, wfh, wfl, bf, lf);
        return;
    }

    const int nmat = blockIdx.x >> 3;
    const int nloc = (blockIdx.x & 7) * 128;
    const int m0 = blockIdx.y * 128;

    const __half* a_h = xh + (size_t)m0 * DD;
    const __half* b_h = ((nmat == 0) ? wqh : (nmat == 1) ? wkh : wvh)
                        + (size_t)nloc * DD;
    __half* Chi = (nmat == 0) ? qhi : (nmat == 1) ? khi : vhi;

    gemm1p_body(smb, smraw, tid, a_h, b_h,
        [&](float acc[4][8][4], int wm, int wn, int lane, int wid) {
            __syncthreads();
            char* Sh = smraw;
            const int r0 = lane >> 2;
            const int cpair = (lane & 3) * 2;
#pragma unroll
            for (int mt = 0; mt < 4; mt++) {
#pragma unroll
                for (int nt = 0; nt < 8; nt++) {
                    const int row0 = wm + mt * 16 + r0;
                    const int col  = wn + nt * 8 + cpair;
                    *(uint32_t*)(Sh + row0 * 272 + col * 2) =
                        pack_h(acc[mt][nt][0], acc[mt][nt][1]);
                    *(uint32_t*)(Sh + (row0 + 8) * 272 + col * 2) =
                        pack_h(acc[mt][nt][2], acc[mt][nt][3]);
                }
            }
            __syncthreads();

            const int g  = lane >> 3;
            const int ck = lane & 7;
#pragma unroll
            for (int p = 0; p < 16; p++) {
                int flat = p * 16 + wid * 4 + g;   // 0..255
                int hh  = flat >> 7;
                int mm  = flat & 127;
                uint4 v = *(uint4*)(Sh + mm * 272 + hh * 128 + ck * 16);
                const int m = m0 + mm;
                const int b = m >> 11;
                const int t = m & (TT - 1);
                const int h = (nloc >> 6) + hh;
                __half* dst = Chi
                            + (((size_t)((b * HH + h) * TT + t)) << 6) + ck * 8;
                *(uint4*)dst = v;
            }
        });
}

// ---------------------------------------------------------------------------
// Output GEMM
// ---------------------------------------------------------------------------
__global__ __launch_bounds__(128, 2) void gemm_out(
    const __half* __restrict__ Ah,
    const __half* __restrict__ Bhi,
    float* __restrict__ Cf)
{
    extern __shared__ char smraw[];
    const uint32_t smb = smem_u32(smraw);
    const int tid = threadIdx.x;
    const int n0 = blockIdx.x * 128;
    const int m0 = blockIdx.y * 128;

    const __half* a_h = Ah + (size_t)m0 * DD;
    const __half* b_h = Bhi + (size_t)n0 * DD;

    gemm1p_body(smb, smraw, tid, a_h, b_h,
        [&](float acc[4][8][4], int wm, int wn, int lane, int wid) {
            (void)wid;
            const int r0 = lane >> 2;
            const int cpair = (lane & 3) * 2;
#pragma unroll
            for (int mt = 0; mt < 4; mt++) {
#pragma unroll
                for (int nt = 0; nt < 8; nt++) {
                    const int m = m0 + wm + mt * 16 + r0;
                    const int n = n0 + wn + nt * 8 + cpair;
                    float* dst0 = Cf + (size_t)m * DD + n;
                    float* dst1 = Cf + (size_t)(m + 8) * DD + n;
                    *(float2*)dst0 = make_float2(acc[mt][nt][0], acc[mt][nt][1]);
                    *(float2*)dst1 = make_float2(acc[mt][nt][2], acc[mt][nt][3]);
                }
            }
        });
}

// ---------------------------------------------------------------------------
// Cumsum over T per (b,h)
// ---------------------------------------------------------------------------
__global__ __launch_bounds__(256) void cumsum_kernel(float* __restrict__ lf)
{
    const int bh = blockIdx.x;
    float* p = lf + (size_t)bh * TT;
    const int tid = threadIdx.x;
    const int lane = tid & 31, wid = tid >> 5;
    __shared__ float wsum[8];

    float v[8];
    float s = 0.f;
#pragma unroll
    for (int i = 0; i < 8; i++) { v[i] = p[tid * 8 + i]; s += v[i]; }

    float ss = s;
#pragma unroll
    for (int off = 1; off < 32; off <<= 1) {
        float n = __shfl_up_sync(0xffffffffu, ss, off);
        if (lane >= off) ss += n;
    }
    if (lane == 31) wsum[wid] = ss;
    __syncthreads();
    float woff = 0.f;
#pragma unroll
    for (int w = 0; w < 8; w++)
        if (w < wid) woff += wsum[w];

    float run = woff + ss - s;
#pragma unroll
    for (int i = 0; i < 8; i++) { run += v[i]; p[tid * 8 + i] = run; }
}

// ---------------------------------------------------------------------------
// HMMA forgetting attention: 64 q-rows/block, pure-fp16 Q/K/V (P stays split).
// QK^T = qh*kh (1 product); PV = (ph+pl)*vh (2 products).
// Stage = {Kh, Vh, cks} = 16.6KB; 3 CTAs/SM.
// ---------------------------------------------------------------------------
#define ATILE  8192
#define ACKS   (2*ATILE)
#define ASTAGE (2*ATILE + 256)          // 16640
#define AQOFF  (2*ASTAGE)               // 33280
#define ATTN_SMEM (2*ASTAGE + ATILE)    // 41472

__device__ __forceinline__ void attn_stage(
    uint32_t sb,
    const __half* Kh, const __half* Vh,
    const float* cptr, int k0, int tid)
{
    const __half* mats[2] = { Kh + (size_t)k0 * HD, Vh + (size_t)k0 * HD };
#pragma unroll
    for (int mt = 0; mt < 2; mt++) {
#pragma unroll
        for (int i = 0; i < 4; i++) {
            int s = tid + i * 128;
            int row = s >> 3, c = s & 7;
            cp16(sb + mt * ATILE + asw(row, c), mats[mt] + row * HD + c * 8);
        }
    }
    if (tid < 16) cp16(sb + ACKS + tid * 16, cptr + k0 + tid * 4);
}

__global__ __launch_bounds__(128, 3) void attn_mma(
    const __half* __restrict__ Qhi,
    const __half* __restrict__ Khi,
    const __half* __restrict__ Vhi,
    const float* __restrict__ C,
    __half* __restrict__ Ohi)
{
    extern __shared__ char smraw[];
    const uint32_t smb = smem_u32(smraw);

    const int tid  = threadIdx.x;
    const int wid  = tid >> 5;
    const int lane = tid & 31;
    const int qt = blockIdx.x;
    const int bh = blockIdx.y;
    const int q0 = qt * 64;

    const __half* Qh = Qhi + (size_t)bh * TT * HD;
    const __half* Kh = Khi + (size_t)bh * TT * HD;
    const __half* Vh = Vhi + (size_t)bh * TT * HD;
    const float* cptr = C + (size_t)bh * TT;

    int kt_start;
    {
        const float cq0v = cptr[q0];
        int lo = 0, hi = qt;
        while (lo < hi) {
            int mid = (lo + hi) >> 1;
            if (cq0v - cptr[mid * 64 + 63] >= -32.f) hi = mid;
            else lo = mid + 1;
        }
        kt_start = lo;
    }

    // group 0: Q hi tile (512 cp16 / 128 thr = 4 each)
#pragma unroll
    for (int i = 0; i < 4; i++) {
        int s = tid + i * 128;
        int row = s >> 3, c = s & 7;
        cp16(smb + AQOFF + asw(row, c),
             Qh + (size_t)(q0 + row) * HD + c * 8);
    }
    cp_commit();
    // group 1: first K/V stage
    attn_stage(smb + (kt_start & 1) * ASTAGE, Kh, Vh, cptr,
               kt_start * 64, tid);
    cp_commit();

    cp_wait<1>();
    __syncthreads();

    const int a_row = lane & 15;
    const int a_chk = lane >> 4;
    uint32_t qh[4][4];
#pragma unroll
    for (int ks = 0; ks < 4; ks++)
        ldmx4(qh[ks], smb + AQOFF + asw(wid * 16 + a_row, ks * 2 + a_chk));

    const int r0 = wid * 16 + (lane >> 2);
    const float cq0 = cptr[q0 + r0];
    const float cq1 = cptr[q0 + r0 + 8];

    float m0 = -1e30f, m1 = -1e30f, l0 = 0.f, l1 = 0.f;
    float o[8][4];
#pragma unroll
    for (int i = 0; i < 8; i++)
#pragma unroll
        for (int j = 0; j < 4; j++) o[i][j] = 0.f;

    const int b_mat = lane >> 3;
    const int b_row = (b_mat >> 1) * 8 + (lane & 7);
    const int b_chk = b_mat & 1;
    const int v_g = lane >> 3;
    const int v_r = lane & 7;

    for (int kt = kt_start; kt <= qt; kt++) {
        if (kt < qt) {
            attn_stage(smb + ((kt + 1) & 1) * ASTAGE,
                       Kh, Vh, cptr, (kt + 1) * 64, tid);
            cp_commit();
            cp_wait<1>();
        } else {
            cp_wait<0>();
        }
        __syncthreads();

        const uint32_t sb = smb + (kt & 1) * ASTAGE;
        const float* cks = (const float*)(smraw + (kt & 1) * ASTAGE + ACKS);

        float s[8][4];
#pragma unroll
        for (int i = 0; i < 8; i++)
#pragma unroll
            for (int j = 0; j < 4; j++) s[i][j] = 0.f;

#pragma unroll
        for (int ks = 0; ks < 4; ks++) {
            uint32_t kh[4][4];
#pragma unroll
            for (int ng = 0; ng < 4; ng++)
                ldmx4(kh[ng], sb + asw(ng * 16 + b_row, ks * 2 + b_chk));
#pragma unroll
            for (int ng = 0; ng < 4; ng++)
#pragma unroll
                for (int h = 0; h < 2; h++)
                    mma16816(s[ng * 2 + h], qh[ks],
                             kh[ng][h * 2], kh[ng][h * 2 + 1]);
        }

        const bool diag = (kt == qt);
        const int k0g = kt * 64;
#pragma unroll
        for (int nt = 0; nt < 8; nt++) {
            const int col = nt * 8 + (lane & 3) * 2;
            const float ck0 = cks[col], ck1 = cks[col + 1];
            float d00 = fmaxf(cq0 - ck0, -50.f);
            float d01 = fmaxf(cq0 - ck1, -50.f);
            float d10 = fmaxf(cq1 - ck0, -50.f);
            float d11 = fmaxf(cq1 - ck1, -50.f);
            s[nt][0] = fmaf(s[nt][0], 0.125f, d00);
            s[nt][1] = fmaf(s[nt][1], 0.125f, d01);
            s[nt][2] = fmaf(s[nt][2], 0.125f, d10);
            s[nt][3] = fmaf(s[nt][3], 0.125f, d11);
            if (diag) {
                if (k0g + col     > q0 + r0)     s[nt][0] = -1e30f;
                if (k0g + col + 1 > q0 + r0)     s[nt][1] = -1e30f;
                if (k0g + col     > q0 + r0 + 8) s[nt][2] = -1e30f;
                if (k0g + col + 1 > q0 + r0 + 8) s[nt][3] = -1e30f;
            }
        }

        float ml0 = -1e30f, ml1 = -1e30f;
#pragma unroll
        for (int nt = 0; nt < 8; nt++) {
            ml0 = fmaxf(ml0, fmaxf(s[nt][0], s[nt][1]));
            ml1 = fmaxf(ml1, fmaxf(s[nt][2], s[nt][3]));
        }
        ml0 = fmaxf(ml0, __shfl_xor_sync(0xffffffffu, ml0, 1));
        ml0 = fmaxf(ml0, __shfl_xor_sync(0xffffffffu, ml0, 2));
        ml1 = fmaxf(ml1, __shfl_xor_sync(0xffffffffu, ml1, 1));
        ml1 = fmaxf(ml1, __shfl_xor_sync(0xffffffffu, ml1, 2));
        const float mn0 = fmaxf(m0, ml0);
        const float mn1 = fmaxf(m1, ml1);
        const float corr0 = ex2f((m0 - mn0) * LOG2E);
        const float corr1 = ex2f((m1 - mn1) * LOG2E);
        m0 = mn0; m1 = mn1;

        float sum0 = 0.f, sum1 = 0.f;
#pragma unroll
        for (int nt = 0; nt < 8; nt++) {
            s[nt][0] = ex2f((s[nt][0] - mn0) * LOG2E);
            s[nt][1] = ex2f((s[nt][1] - mn0) * LOG2E);
            s[nt][2] = ex2f((s[nt][2] - mn1) * LOG2E);
            s[nt][3] = ex2f((s[nt][3] - mn1) * LOG2E);
            sum0 += s[nt][0] + s[nt][1];
            sum1 += s[nt][2] + s[nt][3];
        }
        l0 = l0 * corr0 + sum0;
        l1 = l1 * corr1 + sum1;
#pragma unroll
        for (int nt = 0; nt < 8; nt++) {
            o[nt][0] *= corr0; o[nt][1] *= corr0;
            o[nt][2] *= corr1; o[nt][3] *= corr1;
        }

        uint32_t ph[4][4], pl[4][4];
#pragma unroll
        for (int kc = 0; kc < 4; kc++) {
            pack_split(s[kc*2][0],   s[kc*2][1],   ph[kc][0], pl[kc][0]);
            pack_split(s[kc*2][2],   s[kc*2][3],   ph[kc][1], pl[kc][1]);
            pack_split(s[kc*2+1][0], s[kc*2+1][1], ph[kc][2], pl[kc][2]);
            pack_split(s[kc*2+1][2], s[kc*2+1][3], ph[kc][3], pl[kc][3]);
        }

#pragma unroll
        for (int kc = 0; kc < 4; kc++) {
            uint32_t vh[4][4];
#pragma unroll
            for (int p = 0; p < 4; p++) {
                int row = kc * 16 + (v_g & 1) * 8 + v_r;
                int chunk = p * 2 + (v_g >> 1);
                ldmx4t(vh[p], sb + ATILE + asw(row, chunk));
            }
#pragma unroll
            for (int p = 0; p < 4; p++)
#pragma unroll
                for (int h = 0; h < 2; h++) {
                    float* c = o[p * 2 + h];
                    mma16816(c, ph[kc], vh[p][h * 2], vh[p][h * 2 + 1]);
                    mma16816(c, pl[kc], vh[p][h * 2], vh[p][h * 2 + 1]);
                }
        }
        __syncthreads();
    }

    l0 += __shfl_xor_sync(0xffffffffu, l0, 1);
    l0 += __shfl_xor_sync(0xffffffffu, l0, 2);
    l1 += __shfl_xor_sync(0xffffffffu, l1, 1);
    l1 += __shfl_xor_sync(0xffffffffu, l1, 2);
    const float inv0 = 1.f / l0;
    const float inv1 = 1.f / l1;

    const int b = bh >> 4, h = bh & 15;
    const int t0 = q0 + r0;
    size_t base0 = ((size_t)(b * TT + t0)) * DD + h * HD;
    size_t base1 = base0 + (size_t)8 * DD;
#pragma unroll
    for (int nt = 0; nt < 8; nt++) {
        const int col = nt * 8 + (lane & 3) * 2;
        *(uint32_t*)(Ohi + base0 + col) = pack_h(o[nt][0] * inv0, o[nt][1] * inv0);
        *(uint32_t*)(Ohi + base1 + col) = pack_h(o[nt][2] * inv1, o[nt][3] * inv1);
    }
}

// ---------------------------------------------------------------------------
// kernel_launch
// ---------------------------------------------------------------------------
extern "C" void kernel_launch(void* const* d_in, const int* in_sizes, int n_in,
                              void* d_out, int out_size)
{
    (void)in_sizes; (void)n_in; (void)out_size;
    const float* x  = (const float*)d_in[0];
    const float* Wq = (const float*)d_in[1];
    const float* Wk = (const float*)d_in[2];
    const float* Wv = (const float*)d_in[3];
    const float* Wo = (const float*)d_in[4];
    const float* Wf = (const float*)d_in[5];
    const float* bf = (const float*)d_in[6];
    float* out = (float*)d_out;

    float* cp;
    cudaGetSymbolAddress((void**)&cp, g_c);

    __half *xhi, *xlo, *ohi;
    __half *qhi, *khi, *vhi;
    __half *wqh, *wkh, *wvh, *woh, *wfth, *wftl;
    cudaGetSymbolAddress((void**)&xhi, g_xhi);
    cudaGetSymbolAddress((void**)&xlo, g_xlo);
    cudaGetSymbolAddress((void**)&ohi, g_ohi);
    cudaGetSymbolAddress((void**)&qhi, g_qhi);
    cudaGetSymbolAddress((void**)&khi, g_khi);
    cudaGetSymbolAddress((void**)&vhi, g_vhi);
    cudaGetSymbolAddress((void**)&wqh, g_wqh);
    cudaGetSymbolAddress((void**)&wkh, g_wkh);
    cudaGetSymbolAddress((void**)&wvh, g_wvh);
    cudaGetSymbolAddress((void**)&woh, g_woh);
    cudaGetSymbolAddress((void**)&wfth, g_wfth);
    cudaGetSymbolAddress((void**)&wftl, g_wftl);

    cudaFuncSetAttribute(gemm_qkv_forget,
                         cudaFuncAttributeMaxDynamicSharedMemorySize, GEMM_SMEM);
    cudaFuncSetAttribute(gemm_out,
                         cudaFuncAttributeMaxDynamicSharedMemorySize, GEMM_SMEM);
    cudaFuncSetAttribute(attn_mma,
                         cudaFuncAttributeMaxDynamicSharedMemorySize, ATTN_SMEM);

    prep_kernel<<<8256, 256>>>(x, Wq, Wk, Wv, Wo, Wf,
                               xhi, xlo, wqh, wkh, wvh, woh, wfth, wftl);

    gemm_qkv_forget<<<dim3(25, 32), 128, GEMM_SMEM>>>(
        xhi, xlo, wqh, wkh, wvh, wfth, wftl, bf, cp,
        qhi, khi, vhi);

    cumsum_kernel<<<BB * HH, 256>>>(cp);

    attn_mma<<<dim3(TT / 64, BB * HH), 128, ATTN_SMEM>>>(
        qhi, khi, vhi, cp, ohi);

    gemm_out<<<dim3(DD / 128, MM / 128), 128, GEMM_SMEM>>>(
        ohi, woh, out);
}